// round 1
// baseline (speedup 1.0000x reference)
#include <cuda_runtime.h>

#define BB  2
#define CH  8
#define AM  8
#define NHH 8
#define FF  256
#define WW  768
#define DHH 32
#define CA  16   // CH + AM

#define YSZ (BB*AM*FF*WW)         // 3,145,728
#define OUT_ELEMS (BB*CH*FF*WW)   // 3,145,728
#define QK_ELEMS  ((size_t)BB*AM*NHH*WW*WW)  // 75,497,472

// ---- scratch (static device memory; allocation is forbidden) ----
__device__ float g_yq[YSZ];
__device__ float g_yk[YSZ];
__device__ float g_yv[YSZ];
__device__ float g_q [YSZ];   // (b,m,h,w,d)
__device__ float g_k [YSZ];
__device__ float g_v [YSZ];
__device__ float g_a [YSZ];   // attention result in (b,m,f,w) layout
__device__ float g_o1[BB*CA*FF*WW];  // positionwise o-proj result

// =====================================================================
// K1: 3x3 conv (pad 1) + bias for q,k,v simultaneously.
// grid (W/256, F, B*AM), block 256
// =====================================================================
__global__ __launch_bounds__(256)
void conv_kernel(const float* __restrict__ x,
                 const float* __restrict__ qcw, const float* __restrict__ qcb,
                 const float* __restrict__ kcw, const float* __restrict__ kcb,
                 const float* __restrict__ vcw, const float* __restrict__ vcb)
{
    int w  = blockIdx.x * 256 + threadIdx.x;
    int f  = blockIdx.y;
    int bm = blockIdx.z;
    int m = bm % AM, b = bm / AM;

    __shared__ float swq[CH*9], swk[CH*9], swv[CH*9];
    __shared__ float sb[3];
    int t = threadIdx.x;
    if (t < CH*9) {
        swq[t] = qcw[m*CH*9 + t];
        swk[t] = kcw[m*CH*9 + t];
        swv[t] = vcw[m*CH*9 + t];
    }
    if (t == 0) { sb[0] = qcb[m]; sb[1] = kcb[m]; sb[2] = vcb[m]; }
    __syncthreads();

    float aq = sb[0], ak = sb[1], av = sb[2];
    #pragma unroll
    for (int ci = 0; ci < CH; ci++) {
        const float* xp = x + (size_t)((b*CH + ci)*FF) * WW;
        #pragma unroll
        for (int kh = 0; kh < 3; kh++) {
            int ff = f + kh - 1;
            if (ff < 0 || ff >= FF) continue;
            #pragma unroll
            for (int kw = 0; kw < 3; kw++) {
                int ww2 = w + kw - 1;
                if (ww2 < 0 || ww2 >= WW) continue;
                float xv = xp[ff*WW + ww2];
                int wi = ci*9 + kh*3 + kw;
                aq = fmaf(xv, swq[wi], aq);
                ak = fmaf(xv, swk[wi], ak);
                av = fmaf(xv, swv[wi], av);
            }
        }
    }
    int oidx = ((b*AM + m)*FF + f)*WW + w;
    g_yq[oidx] = aq; g_yk[oidx] = ak; g_yv[oidx] = av;
}

// =====================================================================
// K2: positionwise linear (per-map 256x256 GEMM over columns) fused with
// head split + RoPE (for q,k). C[g,w] = sum_f pw[m][g,f] * y[b,m,f,w]
// Tile 64x64, BK=16, 256 threads, 4x4 microtile.
// grid (F/64, W/64, 3*B*AM)
// =====================================================================
__global__ __launch_bounds__(256)
void pw_kernel(const float* __restrict__ qpw,
               const float* __restrict__ kpw,
               const float* __restrict__ vpw)
{
    int z  = blockIdx.z;
    int p  = z / (BB*AM);     // 0=q 1=k 2=v
    int bm = z % (BB*AM);
    int b = bm / AM, m = bm % AM;

    const float* A  = (p == 0 ? qpw : (p == 1 ? kpw : vpw)) + (size_t)m*FF*FF;   // (g,f)
    const float* Bm = (p == 0 ? g_yq : (p == 1 ? g_yk : g_yv)) + (size_t)(b*AM + m)*FF*WW; // (f,w)
    float*       Out = (p == 0 ? g_q : (p == 1 ? g_k : g_v)) + (size_t)(b*AM + m)*NHH*WW*DHH;

    __shared__ float As[16][68];   // [f][g]
    __shared__ float Bs[16][68];   // [f][w]

    int g0 = blockIdx.x * 64, w0 = blockIdx.y * 64;
    int tid = threadIdx.x;
    int ty = tid / 16, tx = tid % 16;

    float acc[4][4] = {};

    for (int f0 = 0; f0 < FF; f0 += 16) {
        {   // A tile 64g x 16f, store transposed [f][g]
            int r  = tid / 4;
            int c4 = (tid % 4) * 4;
            float4 v4 = *reinterpret_cast<const float4*>(&A[(size_t)(g0 + r)*FF + f0 + c4]);
            As[c4+0][r] = v4.x; As[c4+1][r] = v4.y; As[c4+2][r] = v4.z; As[c4+3][r] = v4.w;
        }
        {   // B tile 16f x 64w
            int r  = tid / 16;
            int c4 = (tid % 16) * 4;
            float4 v4 = *reinterpret_cast<const float4*>(&Bm[(size_t)(f0 + r)*WW + w0 + c4]);
            *reinterpret_cast<float4*>(&Bs[r][c4]) = v4;
        }
        __syncthreads();
        #pragma unroll
        for (int kk = 0; kk < 16; kk++) {
            float4 a4 = *reinterpret_cast<const float4*>(&As[kk][ty*4]);
            float4 b4 = *reinterpret_cast<const float4*>(&Bs[kk][tx*4]);
            acc[0][0] = fmaf(a4.x, b4.x, acc[0][0]); acc[0][1] = fmaf(a4.x, b4.y, acc[0][1]);
            acc[0][2] = fmaf(a4.x, b4.z, acc[0][2]); acc[0][3] = fmaf(a4.x, b4.w, acc[0][3]);
            acc[1][0] = fmaf(a4.y, b4.x, acc[1][0]); acc[1][1] = fmaf(a4.y, b4.y, acc[1][1]);
            acc[1][2] = fmaf(a4.y, b4.z, acc[1][2]); acc[1][3] = fmaf(a4.y, b4.w, acc[1][3]);
            acc[2][0] = fmaf(a4.z, b4.x, acc[2][0]); acc[2][1] = fmaf(a4.z, b4.y, acc[2][1]);
            acc[2][2] = fmaf(a4.z, b4.z, acc[2][2]); acc[2][3] = fmaf(a4.z, b4.w, acc[2][3]);
            acc[3][0] = fmaf(a4.w, b4.x, acc[3][0]); acc[3][1] = fmaf(a4.w, b4.y, acc[3][1]);
            acc[3][2] = fmaf(a4.w, b4.z, acc[3][2]); acc[3][3] = fmaf(a4.w, b4.w, acc[3][3]);
        }
        __syncthreads();
    }

    if (p == 2) {
        #pragma unroll
        for (int i = 0; i < 4; i++) {
            int g = g0 + ty*4 + i;
            int h = g >> 5, d = g & 31;
            #pragma unroll
            for (int j = 0; j < 4; j++) {
                int w = w0 + tx*4 + j;
                Out[((size_t)h*WW + w)*DHH + d] = acc[i][j];
            }
        }
    } else {
        // RoPE: rows come in even/odd pairs (g0, ty*4 are multiples of 4)
        #pragma unroll
        for (int i = 0; i < 4; i += 2) {
            int ge = g0 + ty*4 + i;          // even
            int de = ge & 31;
            int h  = ge >> 5;
            // inv = 10000^{-de/32}
            float inv = expf(-(float)de * (9.210340371976184f / 32.0f));
            #pragma unroll
            for (int j = 0; j < 4; j++) {
                int w = w0 + tx*4 + j;
                float th = (float)w * inv;
                float s, c;
                sincosf(th, &s, &c);
                float ve = acc[i][j], vo = acc[i+1][j];
                Out[((size_t)h*WW + w)*DHH + de    ] = ve*c - vo*s;
                Out[((size_t)h*WW + w)*DHH + de + 1] = vo*c + ve*s;
            }
        }
    }
}

// =====================================================================
// K3: qk = Q@K^T / 16 + prev_qk   (128 batches of 768x768x32)
// Tile 64x64, full K=32 in smem. grid (12 ktile, 12 qtile, 128)
// =====================================================================
__global__ __launch_bounds__(256)
void qk_kernel(const float* __restrict__ prev_qk, float* __restrict__ qk_out)
{
    int batch = blockIdx.z;
    const float* Q = g_q + (size_t)batch*WW*DHH;
    const float* K = g_k + (size_t)batch*WW*DHH;
    int k0 = blockIdx.x * 64, q0 = blockIdx.y * 64;

    __shared__ float Qs[32][68];  // [d][q]
    __shared__ float Ks[32][68];  // [d][k]
    int tid = threadIdx.x;

    #pragma unroll
    for (int it = 0; it < 2; it++) {
        int li = tid + it*256;          // 0..511
        int r  = li / 8;
        int c4 = (li % 8) * 4;
        float4 v4 = *reinterpret_cast<const float4*>(&Q[(size_t)(q0 + r)*DHH + c4]);
        Qs[c4+0][r] = v4.x; Qs[c4+1][r] = v4.y; Qs[c4+2][r] = v4.z; Qs[c4+3][r] = v4.w;
        float4 u4 = *reinterpret_cast<const float4*>(&K[(size_t)(k0 + r)*DHH + c4]);
        Ks[c4+0][r] = u4.x; Ks[c4+1][r] = u4.y; Ks[c4+2][r] = u4.z; Ks[c4+3][r] = u4.w;
    }
    __syncthreads();

    int ty = tid / 16, tx = tid % 16;
    float acc[4][4] = {};
    #pragma unroll
    for (int d = 0; d < 32; d++) {
        float4 a4 = *reinterpret_cast<const float4*>(&Qs[d][ty*4]);
        float4 b4 = *reinterpret_cast<const float4*>(&Ks[d][tx*4]);
        acc[0][0] = fmaf(a4.x, b4.x, acc[0][0]); acc[0][1] = fmaf(a4.x, b4.y, acc[0][1]);
        acc[0][2] = fmaf(a4.x, b4.z, acc[0][2]); acc[0][3] = fmaf(a4.x, b4.w, acc[0][3]);
        acc[1][0] = fmaf(a4.y, b4.x, acc[1][0]); acc[1][1] = fmaf(a4.y, b4.y, acc[1][1]);
        acc[1][2] = fmaf(a4.y, b4.z, acc[1][2]); acc[1][3] = fmaf(a4.y, b4.w, acc[1][3]);
        acc[2][0] = fmaf(a4.z, b4.x, acc[2][0]); acc[2][1] = fmaf(a4.z, b4.y, acc[2][1]);
        acc[2][2] = fmaf(a4.z, b4.z, acc[2][2]); acc[2][3] = fmaf(a4.z, b4.w, acc[2][3]);
        acc[3][0] = fmaf(a4.w, b4.x, acc[3][0]); acc[3][1] = fmaf(a4.w, b4.y, acc[3][1]);
        acc[3][2] = fmaf(a4.w, b4.z, acc[3][2]); acc[3][3] = fmaf(a4.w, b4.w, acc[3][3]);
    }

    const float scale = 1.0f / 16.0f;
    size_t base = (size_t)batch * WW * WW;
    #pragma unroll
    for (int i = 0; i < 4; i++) {
        int q = q0 + ty*4 + i;
        size_t row = base + (size_t)q*WW + k0 + tx*4;
        float4 pv = *reinterpret_cast<const float4*>(&prev_qk[row]);
        float4 o;
        o.x = fmaf(acc[i][0], scale, pv.x);
        o.y = fmaf(acc[i][1], scale, pv.y);
        o.z = fmaf(acc[i][2], scale, pv.z);
        o.w = fmaf(acc[i][3], scale, pv.w);
        *reinterpret_cast<float4*>(&qk_out[row]) = o;
    }
}

// =====================================================================
// K4: softmax over k (768) + P@V (768x32), one warp per q-row,
// 8 rows per block. grid (W/8, 128), block 256.
// Result written coalesced into g_a (b,m,f,w) via smem transpose.
// =====================================================================
__global__ __launch_bounds__(256)
void softmax_av_kernel(const float* __restrict__ qk)
{
    int batch = blockIdx.y;
    int b  = batch / (AM*NHH);
    int mh = batch % (AM*NHH);
    int m = mh / NHH, h = mh % NHH;
    int qrow0 = blockIdx.x * 8;
    int warp = threadIdx.x >> 5, lane = threadIdx.x & 31;
    int qrow = qrow0 + warp;

    __shared__ float p_sh[8][WW];   // 24 KB
    __shared__ float a_sh[DHH][8];  // 1 KB

    // ---- phase 1: softmax ----
    const float* rp = qk + ((size_t)batch*WW + qrow) * WW;
    float v[24];
    float mx = -1e30f;
    #pragma unroll
    for (int j = 0; j < 24; j++) { v[j] = rp[lane + j*32]; mx = fmaxf(mx, v[j]); }
    #pragma unroll
    for (int o = 16; o > 0; o >>= 1) mx = fmaxf(mx, __shfl_xor_sync(0xffffffffu, mx, o));
    float sum = 0.f;
    #pragma unroll
    for (int j = 0; j < 24; j++) { v[j] = __expf(v[j] - mx); sum += v[j]; }
    #pragma unroll
    for (int o = 16; o > 0; o >>= 1) sum += __shfl_xor_sync(0xffffffffu, sum, o);
    float rs = 1.0f / sum;
    #pragma unroll
    for (int j = 0; j < 24; j++) p_sh[warp][lane + j*32] = v[j] * rs;
    __syncwarp();

    // ---- phase 2: P @ V,  4 k-rows per iteration via float4 ----
    const float* V = g_v + (size_t)batch*WW*DHH;
    int kk = lane >> 3;          // 0..3  (k sub-row)
    int dq = lane & 7;           // 0..7  (d quad)
    float4 acc = make_float4(0.f, 0.f, 0.f, 0.f);
    #pragma unroll 4
    for (int k = 0; k < WW; k += 4) {
        float4 v4 = *reinterpret_cast<const float4*>(&V[(size_t)(k + kk)*DHH + dq*4]);
        float pk = p_sh[warp][k + kk];
        acc.x = fmaf(pk, v4.x, acc.x);
        acc.y = fmaf(pk, v4.y, acc.y);
        acc.z = fmaf(pk, v4.z, acc.z);
        acc.w = fmaf(pk, v4.w, acc.w);
    }
    // reduce over kk groups (lanes differing in bits 3,4)
    #pragma unroll
    for (int o = 8; o <= 16; o <<= 1) {
        acc.x += __shfl_xor_sync(0xffffffffu, acc.x, o);
        acc.y += __shfl_xor_sync(0xffffffffu, acc.y, o);
        acc.z += __shfl_xor_sync(0xffffffffu, acc.z, o);
        acc.w += __shfl_xor_sync(0xffffffffu, acc.w, o);
    }
    if (lane < 8) {
        a_sh[dq*4 + 0][warp] = acc.x;
        a_sh[dq*4 + 1][warp] = acc.y;
        a_sh[dq*4 + 2][warp] = acc.z;
        a_sh[dq*4 + 3][warp] = acc.w;
    }
    __syncthreads();

    // ---- coalesced write: a[b,m,h*32+d, w0..w0+7] ----
    if (threadIdx.x < 64) {
        int d   = threadIdx.x >> 1;
        int off = (threadIdx.x & 1) * 4;
        float4 o;
        o.x = a_sh[d][off + 0]; o.y = a_sh[d][off + 1];
        o.z = a_sh[d][off + 2]; o.w = a_sh[d][off + 3];
        *reinterpret_cast<float4*>(
            &g_a[((size_t)(b*AM + m)*FF + h*DHH + d)*WW + qrow0 + off]) = o;
    }
}

// =====================================================================
// K5a: o positionwise proj: o1[b,c,g,w] = sum_f xa[b,c,f,w] * o_pw[c,g,f]
// xa channel c<8 comes from x, c>=8 from g_a. Same GEMM tiling as K2.
// grid (F/64, W/64, B*CA)
// =====================================================================
__global__ __launch_bounds__(256)
void opw_kernel(const float* __restrict__ x, const float* __restrict__ opw)
{
    int z = blockIdx.z;
    int b = z / CA, c = z % CA;
    const float* A  = opw + (size_t)c*FF*FF;                          // (g,f)
    const float* Bm = (c < CH) ? (x   + (size_t)(b*CH + c     )*FF*WW)
                               : (g_a + (size_t)(b*AM + c - CH)*FF*WW); // (f,w)
    float* Out = g_o1 + (size_t)(b*CA + c)*FF*WW;

    __shared__ float As[16][68];
    __shared__ float Bs[16][68];

    int g0 = blockIdx.x * 64, w0 = blockIdx.y * 64;
    int tid = threadIdx.x;
    int ty = tid / 16, tx = tid % 16;

    float acc[4][4] = {};
    for (int f0 = 0; f0 < FF; f0 += 16) {
        {
            int r  = tid / 4;
            int c4 = (tid % 4) * 4;
            float4 v4 = *reinterpret_cast<const float4*>(&A[(size_t)(g0 + r)*FF + f0 + c4]);
            As[c4+0][r] = v4.x; As[c4+1][r] = v4.y; As[c4+2][r] = v4.z; As[c4+3][r] = v4.w;
        }
        {
            int r  = tid / 16;
            int c4 = (tid % 16) * 4;
            float4 v4 = *reinterpret_cast<const float4*>(&Bm[(size_t)(f0 + r)*WW + w0 + c4]);
            *reinterpret_cast<float4*>(&Bs[r][c4]) = v4;
        }
        __syncthreads();
        #pragma unroll
        for (int kk = 0; kk < 16; kk++) {
            float4 a4 = *reinterpret_cast<const float4*>(&As[kk][ty*4]);
            float4 b4 = *reinterpret_cast<const float4*>(&Bs[kk][tx*4]);
            acc[0][0] = fmaf(a4.x, b4.x, acc[0][0]); acc[0][1] = fmaf(a4.x, b4.y, acc[0][1]);
            acc[0][2] = fmaf(a4.x, b4.z, acc[0][2]); acc[0][3] = fmaf(a4.x, b4.w, acc[0][3]);
            acc[1][0] = fmaf(a4.y, b4.x, acc[1][0]); acc[1][1] = fmaf(a4.y, b4.y, acc[1][1]);
            acc[1][2] = fmaf(a4.y, b4.z, acc[1][2]); acc[1][3] = fmaf(a4.y, b4.w, acc[1][3]);
            acc[2][0] = fmaf(a4.z, b4.x, acc[2][0]); acc[2][1] = fmaf(a4.z, b4.y, acc[2][1]);
            acc[2][2] = fmaf(a4.z, b4.z, acc[2][2]); acc[2][3] = fmaf(a4.z, b4.w, acc[2][3]);
            acc[3][0] = fmaf(a4.w, b4.x, acc[3][0]); acc[3][1] = fmaf(a4.w, b4.y, acc[3][1]);
            acc[3][2] = fmaf(a4.w, b4.z, acc[3][2]); acc[3][3] = fmaf(a4.w, b4.w, acc[3][3]);
        }
        __syncthreads();
    }
    #pragma unroll
    for (int i = 0; i < 4; i++) {
        int g = g0 + ty*4 + i;
        float4 o = make_float4(acc[i][0], acc[i][1], acc[i][2], acc[i][3]);
        *reinterpret_cast<float4*>(&Out[(size_t)g*WW + w0 + tx*4]) = o;
    }
}

// =====================================================================
// K5b: depthwise channel mix: out[b,d,g,w] = sum_c o_dw[d,c]*o1[b,c,g,w]
// grid (B*F*W/256), block 256
// =====================================================================
__global__ __launch_bounds__(256)
void mix_kernel(const float* __restrict__ o_dw, float* __restrict__ out)
{
    int idx = blockIdx.x * 256 + threadIdx.x;   // over B*F*W
    int b  = idx / (FF*WW);
    int gw = idx % (FF*WW);

    __shared__ float sdw[CH*CA];
    if (threadIdx.x < CH*CA) sdw[threadIdx.x] = o_dw[threadIdx.x];
    __syncthreads();

    float vc[CA];
    #pragma unroll
    for (int c = 0; c < CA; c++)
        vc[c] = g_o1[(size_t)(b*CA + c)*FF*WW + gw];

    #pragma unroll
    for (int d = 0; d < CH; d++) {
        float s = 0.f;
        #pragma unroll
        for (int c = 0; c < CA; c++) s = fmaf(sdw[d*CA + c], vc[c], s);
        out[(size_t)(b*CH + d)*FF*WW + gw] = s;
    }
}

// =====================================================================
extern "C" void kernel_launch(void* const* d_in, const int* in_sizes, int n_in,
                              void* d_out, int out_size)
{
    const float* x       = (const float*)d_in[0];
    const float* prev_qk = (const float*)d_in[1];
    const float* q_cw = (const float*)d_in[2];
    const float* q_cb = (const float*)d_in[3];
    const float* q_pw = (const float*)d_in[4];
    const float* k_cw = (const float*)d_in[5];
    const float* k_cb = (const float*)d_in[6];
    const float* k_pw = (const float*)d_in[7];
    const float* v_cw = (const float*)d_in[8];
    const float* v_cb = (const float*)d_in[9];
    const float* v_pw = (const float*)d_in[10];
    const float* o_pw = (const float*)d_in[11];
    const float* o_dw = (const float*)d_in[12];

    float* out_main = (float*)d_out;                  // (B,CH,F,W)
    float* qk_out   = (float*)d_out + OUT_ELEMS;      // (B,AM,NH,W,W)

    conv_kernel<<<dim3(WW/256, FF, BB*AM), 256>>>(x, q_cw, q_cb, k_cw, k_cb, v_cw, v_cb);
    pw_kernel<<<dim3(FF/64, WW/64, 3*BB*AM), 256>>>(q_pw, k_pw, v_pw);
    qk_kernel<<<dim3(WW/64, WW/64, BB*AM*NHH), 256>>>(prev_qk, qk_out);
    softmax_av_kernel<<<dim3(WW/8, BB*AM*NHH), 256>>>(qk_out);
    opw_kernel<<<dim3(FF/64, WW/64, BB*CA), 256>>>(x, o_pw);
    mix_kernel<<<dim3(BB*FF*WW/256), 256>>>(o_dw, out_main);
}

// round 2
// speedup vs baseline: 1.2930x; 1.2930x over previous
#include <cuda_runtime.h>

#define BB  2
#define CH  8
#define AM  8
#define NHH 8
#define FF  256
#define WW  768
#define DHH 32
#define CA  16   // CH + AM

#define YSZ (BB*AM*FF*WW)         // 3,145,728
#define OUT_ELEMS (BB*CH*FF*WW)   // 3,145,728

// ---- scratch (static device memory; allocation is forbidden) ----
__device__ float g_yq[YSZ];
__device__ float g_yk[YSZ];
__device__ float g_yv[YSZ];
__device__ float g_q [YSZ];   // (b,m,h,w,d)
__device__ float g_k [YSZ];
__device__ float g_v [YSZ];
__device__ float g_a [YSZ];   // attention result in (b,m,f,w) layout
__device__ float g_o1[BB*CA*FF*WW];  // positionwise o-proj result

// ---------- packed f32x2 helpers (sm_103a FFMA2) ----------
__device__ __forceinline__ unsigned long long bc2(float v) {
    unsigned long long r;
    asm("mov.b64 %0, {%1, %1};" : "=l"(r) : "f"(v));
    return r;
}
__device__ __forceinline__ void fma2(unsigned long long& d, unsigned long long a, unsigned long long b) {
    asm("fma.rn.f32x2 %0, %1, %2, %0;" : "+l"(d) : "l"(a), "l"(b));
}
__device__ __forceinline__ void mul2(unsigned long long& d, unsigned long long a) {
    asm("mul.rn.f32x2 %0, %0, %1;" : "+l"(d) : "l"(a));
}
__device__ __forceinline__ float2 up2(unsigned long long v) {
    float lo, hi;
    asm("mov.b64 {%0, %1}, %2;" : "=f"(lo), "=f"(hi) : "l"(v));
    return make_float2(lo, hi);
}

// =====================================================================
// K1: 3x3 conv (pad 1) + bias for q,k,v simultaneously.
// grid (W/256, F, B*AM), block 256
// =====================================================================
__global__ __launch_bounds__(256)
void conv_kernel(const float* __restrict__ x,
                 const float* __restrict__ qcw, const float* __restrict__ qcb,
                 const float* __restrict__ kcw, const float* __restrict__ kcb,
                 const float* __restrict__ vcw, const float* __restrict__ vcb)
{
    int w  = blockIdx.x * 256 + threadIdx.x;
    int f  = blockIdx.y;
    int bm = blockIdx.z;
    int m = bm % AM, b = bm / AM;

    __shared__ float swq[CH*9], swk[CH*9], swv[CH*9];
    __shared__ float sb[3];
    int t = threadIdx.x;
    if (t < CH*9) {
        swq[t] = qcw[m*CH*9 + t];
        swk[t] = kcw[m*CH*9 + t];
        swv[t] = vcw[m*CH*9 + t];
    }
    if (t == 0) { sb[0] = qcb[m]; sb[1] = kcb[m]; sb[2] = vcb[m]; }
    __syncthreads();

    float aq = sb[0], ak = sb[1], av = sb[2];
    #pragma unroll
    for (int ci = 0; ci < CH; ci++) {
        const float* xp = x + (size_t)((b*CH + ci)*FF) * WW;
        #pragma unroll
        for (int kh = 0; kh < 3; kh++) {
            int ff = f + kh - 1;
            if (ff < 0 || ff >= FF) continue;
            #pragma unroll
            for (int kw = 0; kw < 3; kw++) {
                int ww2 = w + kw - 1;
                if (ww2 < 0 || ww2 >= WW) continue;
                float xv = xp[ff*WW + ww2];
                int wi = ci*9 + kh*3 + kw;
                aq = fmaf(xv, swq[wi], aq);
                ak = fmaf(xv, swk[wi], ak);
                av = fmaf(xv, swv[wi], av);
            }
        }
    }
    int oidx = ((b*AM + m)*FF + f)*WW + w;
    g_yq[oidx] = aq; g_yk[oidx] = ak; g_yv[oidx] = av;
}

// =====================================================================
// K2: positionwise linear fused with head split + RoPE (for q,k).
// =====================================================================
__global__ __launch_bounds__(256)
void pw_kernel(const float* __restrict__ qpw,
               const float* __restrict__ kpw,
               const float* __restrict__ vpw)
{
    int z  = blockIdx.z;
    int p  = z / (BB*AM);     // 0=q 1=k 2=v
    int bm = z % (BB*AM);
    int b = bm / AM, m = bm % AM;

    const float* A  = (p == 0 ? qpw : (p == 1 ? kpw : vpw)) + (size_t)m*FF*FF;   // (g,f)
    const float* Bm = (p == 0 ? g_yq : (p == 1 ? g_yk : g_yv)) + (size_t)(b*AM + m)*FF*WW; // (f,w)
    float*       Out = (p == 0 ? g_q : (p == 1 ? g_k : g_v)) + (size_t)(b*AM + m)*NHH*WW*DHH;

    __shared__ float As[16][68];   // [f][g]
    __shared__ float Bs[16][68];   // [f][w]

    int g0 = blockIdx.x * 64, w0 = blockIdx.y * 64;
    int tid = threadIdx.x;
    int ty = tid / 16, tx = tid % 16;

    float acc[4][4] = {};

    for (int f0 = 0; f0 < FF; f0 += 16) {
        {   // A tile 64g x 16f, store transposed [f][g]
            int r  = tid / 4;
            int c4 = (tid % 4) * 4;
            float4 v4 = *reinterpret_cast<const float4*>(&A[(size_t)(g0 + r)*FF + f0 + c4]);
            As[c4+0][r] = v4.x; As[c4+1][r] = v4.y; As[c4+2][r] = v4.z; As[c4+3][r] = v4.w;
        }
        {   // B tile 16f x 64w
            int r  = tid / 16;
            int c4 = (tid % 16) * 4;
            float4 v4 = *reinterpret_cast<const float4*>(&Bm[(size_t)(f0 + r)*WW + w0 + c4]);
            *reinterpret_cast<float4*>(&Bs[r][c4]) = v4;
        }
        __syncthreads();
        #pragma unroll
        for (int kk = 0; kk < 16; kk++) {
            float4 a4 = *reinterpret_cast<const float4*>(&As[kk][ty*4]);
            float4 b4 = *reinterpret_cast<const float4*>(&Bs[kk][tx*4]);
            acc[0][0] = fmaf(a4.x, b4.x, acc[0][0]); acc[0][1] = fmaf(a4.x, b4.y, acc[0][1]);
            acc[0][2] = fmaf(a4.x, b4.z, acc[0][2]); acc[0][3] = fmaf(a4.x, b4.w, acc[0][3]);
            acc[1][0] = fmaf(a4.y, b4.x, acc[1][0]); acc[1][1] = fmaf(a4.y, b4.y, acc[1][1]);
            acc[1][2] = fmaf(a4.y, b4.z, acc[1][2]); acc[1][3] = fmaf(a4.y, b4.w, acc[1][3]);
            acc[2][0] = fmaf(a4.z, b4.x, acc[2][0]); acc[2][1] = fmaf(a4.z, b4.y, acc[2][1]);
            acc[2][2] = fmaf(a4.z, b4.z, acc[2][2]); acc[2][3] = fmaf(a4.z, b4.w, acc[2][3]);
            acc[3][0] = fmaf(a4.w, b4.x, acc[3][0]); acc[3][1] = fmaf(a4.w, b4.y, acc[3][1]);
            acc[3][2] = fmaf(a4.w, b4.z, acc[3][2]); acc[3][3] = fmaf(a4.w, b4.w, acc[3][3]);
        }
        __syncthreads();
    }

    if (p == 2) {
        #pragma unroll
        for (int i = 0; i < 4; i++) {
            int g = g0 + ty*4 + i;
            int h = g >> 5, d = g & 31;
            #pragma unroll
            for (int j = 0; j < 4; j++) {
                int w = w0 + tx*4 + j;
                Out[((size_t)h*WW + w)*DHH + d] = acc[i][j];
            }
        }
    } else {
        #pragma unroll
        for (int i = 0; i < 4; i += 2) {
            int ge = g0 + ty*4 + i;          // even
            int de = ge & 31;
            int h  = ge >> 5;
            float inv = expf(-(float)de * (9.210340371976184f / 32.0f));
            #pragma unroll
            for (int j = 0; j < 4; j++) {
                int w = w0 + tx*4 + j;
                float th = (float)w * inv;
                float s, c;
                sincosf(th, &s, &c);
                float ve = acc[i][j], vo = acc[i+1][j];
                Out[((size_t)h*WW + w)*DHH + de    ] = ve*c - vo*s;
                Out[((size_t)h*WW + w)*DHH + de + 1] = vo*c + ve*s;
            }
        }
    }
}

// =====================================================================
// K3 (fused): flash attention per (batch, q-tile of 64).
//   S = Q@K^T/16 + prev   -> written to qk_out (required output)
//   online softmax + O += P@V, all from smem, f32x2-packed GEMMs.
// grid (12, 128), block 256
// =====================================================================
__global__ __launch_bounds__(256)
void flash_kernel(const float* __restrict__ prev_qk, float* __restrict__ qk_out)
{
    int q0    = blockIdx.x * 64;
    int batch = blockIdx.y;
    const float* Q = g_q + (size_t)batch*WW*DHH;
    const float* K = g_k + (size_t)batch*WW*DHH;
    const float* V = g_v + (size_t)batch*WW*DHH;

    __shared__ float  Qs[32][68];   // [d][q]
    __shared__ float  Ks[32][68];   // [d][k]
    __shared__ float4 Vs[64][8];    // [k][d/4]
    __shared__ float  Ps[64][68];   // P tile; reused as O staging at the end

    int tid = threadIdx.x;
    int ty = tid >> 4, tx = tid & 15;
    int dq = tx & 7, kx = tx >> 3;

    // load Q tile transposed (once)
    #pragma unroll
    for (int it = 0; it < 2; it++) {
        int li = tid + it*256;
        int r = li >> 3, c4 = (li & 7) * 4;
        float4 v4 = *reinterpret_cast<const float4*>(&Q[(size_t)(q0 + r)*DHH + c4]);
        Qs[c4+0][r] = v4.x; Qs[c4+1][r] = v4.y; Qs[c4+2][r] = v4.z; Qs[c4+3][r] = v4.w;
    }

    float m_i[4], l_i[4];
    unsigned long long o2[4][2];
    #pragma unroll
    for (int i = 0; i < 4; i++) { m_i[i] = -1e30f; l_i[i] = 0.f; o2[i][0] = 0ull; o2[i][1] = 0ull; }

    const float scale = 1.f/16.f;
    size_t qkbase = (size_t)batch * WW * WW;

    for (int kt = 0; kt < 12; kt++) {
        int k0 = kt * 64;
        __syncthreads();   // prior AV done with Ks/Vs/Ps
        #pragma unroll
        for (int it = 0; it < 2; it++) {
            int li = tid + it*256;
            int r = li >> 3, c4 = (li & 7) * 4;
            float4 v4 = *reinterpret_cast<const float4*>(&K[(size_t)(k0 + r)*DHH + c4]);
            Ks[c4+0][r] = v4.x; Ks[c4+1][r] = v4.y; Ks[c4+2][r] = v4.z; Ks[c4+3][r] = v4.w;
            float4 u4 = *reinterpret_cast<const float4*>(&V[(size_t)(k0 + r)*DHH + c4]);
            Vs[r][li & 7] = u4;
        }
        __syncthreads();

        // ---- S = Q @ K^T (packed f32x2, cols packed in pairs) ----
        unsigned long long acc2[4][2] = {0ull,0ull,0ull,0ull,0ull,0ull,0ull,0ull};
        #pragma unroll
        for (int d = 0; d < 32; d++) {
            ulonglong2 kk2 = *reinterpret_cast<const ulonglong2*>(&Ks[d][tx*4]);
            float4 qv = *reinterpret_cast<const float4*>(&Qs[d][ty*4]);
            unsigned long long b0 = bc2(qv.x), b1 = bc2(qv.y), b2 = bc2(qv.z), b3 = bc2(qv.w);
            fma2(acc2[0][0], b0, kk2.x); fma2(acc2[0][1], b0, kk2.y);
            fma2(acc2[1][0], b1, kk2.x); fma2(acc2[1][1], b1, kk2.y);
            fma2(acc2[2][0], b2, kk2.x); fma2(acc2[2][1], b2, kk2.y);
            fma2(acc2[3][0], b3, kk2.x); fma2(acc2[3][1], b3, kk2.y);
        }

        // ---- epilogue: scale + prev, write qk, online softmax ----
        #pragma unroll
        for (int i = 0; i < 4; i++) {
            int q = q0 + ty*4 + i;
            size_t row = qkbase + (size_t)q*WW + k0 + tx*4;
            float4 pv = *reinterpret_cast<const float4*>(&prev_qk[row]);
            float2 s01 = up2(acc2[i][0]);
            float2 s23 = up2(acc2[i][1]);
            float s0 = fmaf(s01.x, scale, pv.x);
            float s1 = fmaf(s01.y, scale, pv.y);
            float s2 = fmaf(s23.x, scale, pv.z);
            float s3 = fmaf(s23.y, scale, pv.w);
            *reinterpret_cast<float4*>(&qk_out[row]) = make_float4(s0,s1,s2,s3);

            float mx = fmaxf(fmaxf(s0,s1), fmaxf(s2,s3));
            #pragma unroll
            for (int o = 8; o > 0; o >>= 1) mx = fmaxf(mx, __shfl_xor_sync(0xffffffffu, mx, o));
            float mnew = fmaxf(m_i[i], mx);
            float corr = __expf(m_i[i] - mnew);
            float p0 = __expf(s0 - mnew), p1 = __expf(s1 - mnew);
            float p2 = __expf(s2 - mnew), p3 = __expf(s3 - mnew);
            float rs = (p0 + p1) + (p2 + p3);
            #pragma unroll
            for (int o = 8; o > 0; o >>= 1) rs += __shfl_xor_sync(0xffffffffu, rs, o);
            l_i[i] = l_i[i]*corr + rs;
            m_i[i] = mnew;
            unsigned long long c2 = bc2(corr);
            mul2(o2[i][0], c2); mul2(o2[i][1], c2);
            *reinterpret_cast<float4*>(&Ps[ty*4+i][tx*4]) = make_float4(p0,p1,p2,p3);
        }
        __syncthreads();

        // ---- O += P @ V (thread: 4 q-rows x 4 d-cols, k-half kx) ----
        #pragma unroll
        for (int kb = 0; kb < 8; kb++) {
            int kbase = kx*32 + kb*4;
            float4 pr0 = *reinterpret_cast<const float4*>(&Ps[ty*4+0][kbase]);
            float4 pr1 = *reinterpret_cast<const float4*>(&Ps[ty*4+1][kbase]);
            float4 pr2 = *reinterpret_cast<const float4*>(&Ps[ty*4+2][kbase]);
            float4 pr3 = *reinterpret_cast<const float4*>(&Ps[ty*4+3][kbase]);
            const float* p0f = reinterpret_cast<const float*>(&pr0);
            const float* p1f = reinterpret_cast<const float*>(&pr1);
            const float* p2f = reinterpret_cast<const float*>(&pr2);
            const float* p3f = reinterpret_cast<const float*>(&pr3);
            #pragma unroll
            for (int t = 0; t < 4; t++) {
                ulonglong2 vv = *reinterpret_cast<const ulonglong2*>(&Vs[kbase + t][dq]);
                unsigned long long w0b = bc2(p0f[t]);
                unsigned long long w1b = bc2(p1f[t]);
                unsigned long long w2b = bc2(p2f[t]);
                unsigned long long w3b = bc2(p3f[t]);
                fma2(o2[0][0], w0b, vv.x); fma2(o2[0][1], w0b, vv.y);
                fma2(o2[1][0], w1b, vv.x); fma2(o2[1][1], w1b, vv.y);
                fma2(o2[2][0], w2b, vv.x); fma2(o2[2][1], w2b, vv.y);
                fma2(o2[3][0], w3b, vv.x); fma2(o2[3][1], w3b, vv.y);
            }
        }
    }

    // ---- finalize: reduce k-halves, divide by l, stage, coalesced write ----
    __syncthreads();   // done with Ps as P; reuse as staging [d][q]
    #pragma unroll
    for (int i = 0; i < 4; i++) {
        float2 a01 = up2(o2[i][0]);
        float2 a23 = up2(o2[i][1]);
        a01.x += __shfl_xor_sync(0xffffffffu, a01.x, 8);
        a01.y += __shfl_xor_sync(0xffffffffu, a01.y, 8);
        a23.x += __shfl_xor_sync(0xffffffffu, a23.x, 8);
        a23.y += __shfl_xor_sync(0xffffffffu, a23.y, 8);
        if (kx == 0) {
            float rl = 1.0f / l_i[i];
            int qc = ty*4 + i;
            Ps[dq*4+0][qc] = a01.x * rl;
            Ps[dq*4+1][qc] = a01.y * rl;
            Ps[dq*4+2][qc] = a23.x * rl;
            Ps[dq*4+3][qc] = a23.y * rl;
        }
    }
    __syncthreads();

    int bmi = batch >> 3, h = batch & 7;
    #pragma unroll
    for (int it = 0; it < 2; it++) {
        int li = tid + it*256;         // 0..511 covers 32 d x 16 float4-cols
        int d  = li >> 4;
        int c4 = (li & 15) * 4;
        float4 o = *reinterpret_cast<const float4*>(&Ps[d][c4]);
        *reinterpret_cast<float4*>(
            &g_a[((size_t)bmi*FF + h*DHH + d)*WW + q0 + c4]) = o;
    }
}

// =====================================================================
// K5a: o positionwise proj
// =====================================================================
__global__ __launch_bounds__(256)
void opw_kernel(const float* __restrict__ x, const float* __restrict__ opw)
{
    int z = blockIdx.z;
    int b = z / CA, c = z % CA;
    const float* A  = opw + (size_t)c*FF*FF;                          // (g,f)
    const float* Bm = (c < CH) ? (x   + (size_t)(b*CH + c     )*FF*WW)
                               : (g_a + (size_t)(b*AM + c - CH)*FF*WW); // (f,w)
    float* Out = g_o1 + (size_t)(b*CA + c)*FF*WW;

    __shared__ float As[16][68];
    __shared__ float Bs[16][68];

    int g0 = blockIdx.x * 64, w0 = blockIdx.y * 64;
    int tid = threadIdx.x;
    int ty = tid / 16, tx = tid % 16;

    float acc[4][4] = {};
    for (int f0 = 0; f0 < FF; f0 += 16) {
        {
            int r  = tid / 4;
            int c4 = (tid % 4) * 4;
            float4 v4 = *reinterpret_cast<const float4*>(&A[(size_t)(g0 + r)*FF + f0 + c4]);
            As[c4+0][r] = v4.x; As[c4+1][r] = v4.y; As[c4+2][r] = v4.z; As[c4+3][r] = v4.w;
        }
        {
            int r  = tid / 16;
            int c4 = (tid % 16) * 4;
            float4 v4 = *reinterpret_cast<const float4*>(&Bm[(size_t)(f0 + r)*WW + w0 + c4]);
            *reinterpret_cast<float4*>(&Bs[r][c4]) = v4;
        }
        __syncthreads();
        #pragma unroll
        for (int kk = 0; kk < 16; kk++) {
            float4 a4 = *reinterpret_cast<const float4*>(&As[kk][ty*4]);
            float4 b4 = *reinterpret_cast<const float4*>(&Bs[kk][tx*4]);
            acc[0][0] = fmaf(a4.x, b4.x, acc[0][0]); acc[0][1] = fmaf(a4.x, b4.y, acc[0][1]);
            acc[0][2] = fmaf(a4.x, b4.z, acc[0][2]); acc[0][3] = fmaf(a4.x, b4.w, acc[0][3]);
            acc[1][0] = fmaf(a4.y, b4.x, acc[1][0]); acc[1][1] = fmaf(a4.y, b4.y, acc[1][1]);
            acc[1][2] = fmaf(a4.y, b4.z, acc[1][2]); acc[1][3] = fmaf(a4.y, b4.w, acc[1][3]);
            acc[2][0] = fmaf(a4.z, b4.x, acc[2][0]); acc[2][1] = fmaf(a4.z, b4.y, acc[2][1]);
            acc[2][2] = fmaf(a4.z, b4.z, acc[2][2]); acc[2][3] = fmaf(a4.z, b4.w, acc[2][3]);
            acc[3][0] = fmaf(a4.w, b4.x, acc[3][0]); acc[3][1] = fmaf(a4.w, b4.y, acc[3][1]);
            acc[3][2] = fmaf(a4.w, b4.z, acc[3][2]); acc[3][3] = fmaf(a4.w, b4.w, acc[3][3]);
        }
        __syncthreads();
    }
    #pragma unroll
    for (int i = 0; i < 4; i++) {
        int g = g0 + ty*4 + i;
        float4 o = make_float4(acc[i][0], acc[i][1], acc[i][2], acc[i][3]);
        *reinterpret_cast<float4*>(&Out[(size_t)g*WW + w0 + tx*4]) = o;
    }
}

// =====================================================================
// K5b: depthwise channel mix
// =====================================================================
__global__ __launch_bounds__(256)
void mix_kernel(const float* __restrict__ o_dw, float* __restrict__ out)
{
    int idx = blockIdx.x * 256 + threadIdx.x;   // over B*F*W
    int b  = idx / (FF*WW);
    int gw = idx % (FF*WW);

    __shared__ float sdw[CH*CA];
    if (threadIdx.x < CH*CA) sdw[threadIdx.x] = o_dw[threadIdx.x];
    __syncthreads();

    float vc[CA];
    #pragma unroll
    for (int c = 0; c < CA; c++)
        vc[c] = g_o1[(size_t)(b*CA + c)*FF*WW + gw];

    #pragma unroll
    for (int d = 0; d < CH; d++) {
        float s = 0.f;
        #pragma unroll
        for (int c = 0; c < CA; c++) s = fmaf(sdw[d*CA + c], vc[c], s);
        out[(size_t)(b*CH + d)*FF*WW + gw] = s;
    }
}

// =====================================================================
extern "C" void kernel_launch(void* const* d_in, const int* in_sizes, int n_in,
                              void* d_out, int out_size)
{
    const float* x       = (const float*)d_in[0];
    const float* prev_qk = (const float*)d_in[1];
    const float* q_cw = (const float*)d_in[2];
    const float* q_cb = (const float*)d_in[3];
    const float* q_pw = (const float*)d_in[4];
    const float* k_cw = (const float*)d_in[5];
    const float* k_cb = (const float*)d_in[6];
    const float* k_pw = (const float*)d_in[7];
    const float* v_cw = (const float*)d_in[8];
    const float* v_cb = (const float*)d_in[9];
    const float* v_pw = (const float*)d_in[10];
    const float* o_pw = (const float*)d_in[11];
    const float* o_dw = (const float*)d_in[12];

    float* out_main = (float*)d_out;                  // (B,CH,F,W)
    float* qk_out   = (float*)d_out + OUT_ELEMS;      // (B,AM,NH,W,W)

    conv_kernel<<<dim3(WW/256, FF, BB*AM), 256>>>(x, q_cw, q_cb, k_cw, k_cb, v_cw, v_cb);
    pw_kernel<<<dim3(FF/64, WW/64, 3*BB*AM), 256>>>(q_pw, k_pw, v_pw);
    flash_kernel<<<dim3(WW/64, BB*AM*NHH), 256>>>(prev_qk, qk_out);
    opw_kernel<<<dim3(FF/64, WW/64, BB*CA), 256>>>(x, o_pw);
    mix_kernel<<<dim3(BB*FF*WW/256), 256>>>(o_dw, out_main);
}

// round 3
// speedup vs baseline: 1.4167x; 1.0957x over previous
#include <cuda_runtime.h>

#define BB  2
#define CH  8
#define AM  8
#define NHH 8
#define FF  256
#define WW  768
#define DHH 32
#define CA  16   // CH + AM

#define YSZ (BB*AM*FF*WW)         // 3,145,728
#define OUT_ELEMS (BB*CH*FF*WW)   // 3,145,728

typedef unsigned long long ull;

// ---- scratch (static device memory; allocation is forbidden) ----
__device__ float g_yq[YSZ];
__device__ float g_yk[YSZ];
__device__ float g_yv[YSZ];
__device__ float g_q [YSZ];   // (b,m, g=h*32+d, w)
__device__ float g_k [YSZ];
__device__ float g_v [YSZ];
__device__ float g_a [YSZ];   // attention result (b,m,f,w)
__device__ float g_o1[BB*CA*FF*WW];
__device__ float2 g_cs[16*WW];  // RoPE table: [e][w] -> (cos, sin)

// conv weights in constant memory (uniform LDC path)
__constant__ float c_qcw[AM*CH*9];
__constant__ float c_kcw[AM*CH*9];
__constant__ float c_vcw[AM*CH*9];
__constant__ float c_qcb[AM];
__constant__ float c_kcb[AM];
__constant__ float c_vcb[AM];

// ---------- packed f32x2 helpers ----------
__device__ __forceinline__ ull bc2(float v) {
    ull r; asm("mov.b64 %0, {%1, %1};" : "=l"(r) : "f"(v)); return r;
}
__device__ __forceinline__ ull pk2(float lo, float hi) {
    ull r; asm("mov.b64 %0, {%1, %2};" : "=l"(r) : "f"(lo), "f"(hi)); return r;
}
__device__ __forceinline__ void fma2(ull& d, ull a, ull b) {
    asm("fma.rn.f32x2 %0, %1, %2, %0;" : "+l"(d) : "l"(a), "l"(b));
}
__device__ __forceinline__ float2 up2(ull v) {
    float lo, hi; asm("mov.b64 {%0, %1}, %2;" : "=f"(lo), "=f"(hi) : "l"(v));
    return make_float2(lo, hi);
}

// =====================================================================
// K0: RoPE cos/sin table init
// =====================================================================
__global__ void cs_init_kernel()
{
    int idx = blockIdx.x * 256 + threadIdx.x;
    if (idx >= 16*WW) return;
    int e = idx / WW, w = idx % WW;
    float inv = expf(-(float)(2*e) * (9.210340371976184f / 32.0f));
    float s, c;
    sincosf((float)w * inv, &s, &c);
    g_cs[idx] = make_float2(c, s);
}

// =====================================================================
// K1: 3x3 conv + bias for q,k,v. 2 outputs/thread via f32x2.
// grid (F, B*AM), block 384 (covers 768 w)
// =====================================================================
__global__ __launch_bounds__(384)
void conv_kernel(const float* __restrict__ x)
{
    int tid = threadIdx.x;
    int w0  = tid * 2;
    int f   = blockIdx.x;
    int bm  = blockIdx.y;
    int m = bm % AM, b = bm / AM;

    ull aq = bc2(c_qcb[m]), ak = bc2(c_kcb[m]), av = bc2(c_vcb[m]);

    #pragma unroll
    for (int ci = 0; ci < CH; ci++) {
        const float* xp = x + (size_t)((b*CH + ci)*FF) * WW;
        #pragma unroll
        for (int kh = 0; kh < 3; kh++) {
            int ff = f + kh - 1;
            if (ff < 0 || ff >= FF) continue;
            const float* xr = xp + ff*WW;
            float xm1 = (w0 > 0)      ? xr[w0-1] : 0.f;
            float2 xc = *reinterpret_cast<const float2*>(&xr[w0]);
            float x2  = (w0+2 < WW)   ? xr[w0+2] : 0.f;
            ull pm = pk2(xm1, xc.x);
            ull p0 = pk2(xc.x, xc.y);
            ull pp = pk2(xc.y, x2);
            int wb = m*72 + ci*9 + kh*3;
            fma2(aq, pm, bc2(c_qcw[wb+0])); fma2(aq, p0, bc2(c_qcw[wb+1])); fma2(aq, pp, bc2(c_qcw[wb+2]));
            fma2(ak, pm, bc2(c_kcw[wb+0])); fma2(ak, p0, bc2(c_kcw[wb+1])); fma2(ak, pp, bc2(c_kcw[wb+2]));
            fma2(av, pm, bc2(c_vcw[wb+0])); fma2(av, p0, bc2(c_vcw[wb+1])); fma2(av, pp, bc2(c_vcw[wb+2]));
        }
    }
    int oid = ((b*AM + m)*FF + f)*WW + w0;
    float2 q2 = up2(aq), k2 = up2(ak), v2 = up2(av);
    *reinterpret_cast<float2*>(&g_yq[oid]) = q2;
    *reinterpret_cast<float2*>(&g_yk[oid]) = k2;
    *reinterpret_cast<float2*>(&g_yv[oid]) = v2;
}

// =====================================================================
// K2: positionwise linear, 128x128 tile, 8x8 microtile, f32x2.
// Output layout [g][w]. RoPE via smem cos/sin table for q,k.
// grid (FF/128, WW/128, 3*B*AM), block 256
// =====================================================================
__global__ __launch_bounds__(256, 2)
void pw_kernel(const float* __restrict__ qpw,
               const float* __restrict__ kpw,
               const float* __restrict__ vpw)
{
    int z  = blockIdx.z;
    int p  = z / (BB*AM);     // 0=q 1=k 2=v
    int bm = z % (BB*AM);
    int m  = bm % AM;

    const float* A  = (p == 0 ? qpw : (p == 1 ? kpw : vpw)) + (size_t)m*FF*FF;      // (g,f)
    const float* Bm = (p == 0 ? g_yq : (p == 1 ? g_yk : g_yv)) + (size_t)bm*FF*WW;  // (f,w)
    float*      Out = (p == 0 ? g_q : (p == 1 ? g_k : g_v)) + (size_t)bm*FF*WW;     // (g,w)

    __shared__ float  As[16][132];   // [f][g]
    __shared__ float  Bs[16][132];   // [f][w]
    __shared__ float2 Ts[16][128];   // [e][w-local]

    int g0 = blockIdx.x * 128, w0 = blockIdx.y * 128;
    int tid = threadIdx.x;
    int ty = tid >> 4, tx = tid & 15;

    if (p < 2) {
        #pragma unroll
        for (int it = 0; it < 8; it++) {
            int li = tid + it*256;
            int e = li >> 7, tw = li & 127;
            Ts[e][tw] = g_cs[e*WW + w0 + tw];
        }
    }

    ull acc2[8][4];
    #pragma unroll
    for (int i = 0; i < 8; i++)
        #pragma unroll
        for (int j = 0; j < 4; j++) acc2[i][j] = 0ull;

    for (int f0 = 0; f0 < FF; f0 += 16) {
        __syncthreads();
        #pragma unroll
        for (int it = 0; it < 2; it++) {
            int li = tid + it*256;
            {   // A tile 128g x 16f -> As[f][g]
                int r = li >> 2, c4 = (li & 3) * 4;
                float4 v4 = *reinterpret_cast<const float4*>(&A[(size_t)(g0 + r)*FF + f0 + c4]);
                As[c4+0][r] = v4.x; As[c4+1][r] = v4.y; As[c4+2][r] = v4.z; As[c4+3][r] = v4.w;
            }
            {   // B tile 16f x 128w
                int r = li >> 5, c4 = (li & 31) * 4;
                *reinterpret_cast<float4*>(&Bs[r][c4]) =
                    *reinterpret_cast<const float4*>(&Bm[(size_t)(f0 + r)*WW + w0 + c4]);
            }
        }
        __syncthreads();

        #pragma unroll
        for (int kk = 0; kk < 16; kk++) {
            float4 a0 = *reinterpret_cast<const float4*>(&As[kk][ty*8]);
            float4 a1 = *reinterpret_cast<const float4*>(&As[kk][ty*8 + 4]);
            ulonglong2 b0 = *reinterpret_cast<const ulonglong2*>(&Bs[kk][tx*8]);
            ulonglong2 b1 = *reinterpret_cast<const ulonglong2*>(&Bs[kk][tx*8 + 4]);
            ull av0 = bc2(a0.x), av1 = bc2(a0.y), av2 = bc2(a0.z), av3 = bc2(a0.w);
            ull av4 = bc2(a1.x), av5 = bc2(a1.y), av6 = bc2(a1.z), av7 = bc2(a1.w);
            fma2(acc2[0][0], av0, b0.x); fma2(acc2[0][1], av0, b0.y); fma2(acc2[0][2], av0, b1.x); fma2(acc2[0][3], av0, b1.y);
            fma2(acc2[1][0], av1, b0.x); fma2(acc2[1][1], av1, b0.y); fma2(acc2[1][2], av1, b1.x); fma2(acc2[1][3], av1, b1.y);
            fma2(acc2[2][0], av2, b0.x); fma2(acc2[2][1], av2, b0.y); fma2(acc2[2][2], av2, b1.x); fma2(acc2[2][3], av2, b1.y);
            fma2(acc2[3][0], av3, b0.x); fma2(acc2[3][1], av3, b0.y); fma2(acc2[3][2], av3, b1.x); fma2(acc2[3][3], av3, b1.y);
            fma2(acc2[4][0], av4, b0.x); fma2(acc2[4][1], av4, b0.y); fma2(acc2[4][2], av4, b1.x); fma2(acc2[4][3], av4, b1.y);
            fma2(acc2[5][0], av5, b0.x); fma2(acc2[5][1], av5, b0.y); fma2(acc2[5][2], av5, b1.x); fma2(acc2[5][3], av5, b1.y);
            fma2(acc2[6][0], av6, b0.x); fma2(acc2[6][1], av6, b0.y); fma2(acc2[6][2], av6, b1.x); fma2(acc2[6][3], av6, b1.y);
            fma2(acc2[7][0], av7, b0.x); fma2(acc2[7][1], av7, b0.y); fma2(acc2[7][2], av7, b1.x); fma2(acc2[7][3], av7, b1.y);
        }
    }

    if (p == 2) {
        #pragma unroll
        for (int i = 0; i < 8; i++) {
            int g = g0 + ty*8 + i;
            float r_[8];
            #pragma unroll
            for (int j = 0; j < 4; j++) {
                float2 f2 = up2(acc2[i][j]);
                r_[2*j] = f2.x; r_[2*j+1] = f2.y;
            }
            float* op = &Out[(size_t)g*WW + w0 + tx*8];
            *reinterpret_cast<float4*>(op)     = make_float4(r_[0], r_[1], r_[2], r_[3]);
            *reinterpret_cast<float4*>(op + 4) = make_float4(r_[4], r_[5], r_[6], r_[7]);
        }
    } else {
        #pragma unroll
        for (int ip = 0; ip < 4; ip++) {
            int g = g0 + ty*8 + ip*2;         // even row of pair
            int e = (g & 31) >> 1;
            float re[8], ro[8];
            #pragma unroll
            for (int j = 0; j < 4; j++) {
                float2 ve = up2(acc2[ip*2    ][j]);
                float2 vo = up2(acc2[ip*2 + 1][j]);
                int twa = tx*8 + 2*j;
                float2 csa = Ts[e][twa];
                float2 csb = Ts[e][twa + 1];
                re[2*j]   = ve.x*csa.x - vo.x*csa.y;
                ro[2*j]   = vo.x*csa.x + ve.x*csa.y;
                re[2*j+1] = ve.y*csb.x - vo.y*csb.y;
                ro[2*j+1] = vo.y*csb.x + ve.y*csb.y;
            }
            float* oe = &Out[(size_t)g*WW + w0 + tx*8];
            float* oo = &Out[(size_t)(g+1)*WW + w0 + tx*8];
            *reinterpret_cast<float4*>(oe)     = make_float4(re[0], re[1], re[2], re[3]);
            *reinterpret_cast<float4*>(oe + 4) = make_float4(re[4], re[5], re[6], re[7]);
            *reinterpret_cast<float4*>(oo)     = make_float4(ro[0], ro[1], ro[2], ro[3]);
            *reinterpret_cast<float4*>(oo + 4) = make_float4(ro[4], ro[5], ro[6], ro[7]);
        }
    }
}

// =====================================================================
// K3 (fused): flash attention, max-free online softmax, reg prefetch.
// grid (12, 128), block 256
// =====================================================================
__global__ __launch_bounds__(256)
void flash_kernel(const float* __restrict__ prev_qk, float* __restrict__ qk_out)
{
    int q0    = blockIdx.x * 64;
    int batch = blockIdx.y;
    int bmi = batch >> 3, h = batch & 7;
    size_t gbase = ((size_t)bmi*FF + h*32) * WW;
    const float* Qb = g_q + gbase;   // row d: +d*WW
    const float* Kb = g_k + gbase;
    const float* Vb = g_v + gbase;

    __shared__ float Qs[32][68];   // [d][q]
    __shared__ float Ks[32][68];   // [d][k]
    __shared__ float Vs[64][36];   // [k][d]
    __shared__ float Ps[64][68];   // P tile / final O staging

    int tid = threadIdx.x;
    int ty = tid >> 4, tx = tid & 15;
    int dq = tx & 7, kx = tx >> 3;
    int lr  = tid >> 4;        // 0..15
    int lc4 = (tid & 15) * 4;  // 0..60

    // load Q tile (direct row copy, coalesced)
    #pragma unroll
    for (int it = 0; it < 2; it++) {
        int d = lr + it*16;
        *reinterpret_cast<float4*>(&Qs[d][lc4]) =
            *reinterpret_cast<const float4*>(&Qb[(size_t)d*WW + q0 + lc4]);
    }

    // prefetch K/V for kt=0
    float4 kr0 = *reinterpret_cast<const float4*>(&Kb[(size_t)lr*WW + lc4]);
    float4 kr1 = *reinterpret_cast<const float4*>(&Kb[(size_t)(lr+16)*WW + lc4]);
    float4 vr0 = *reinterpret_cast<const float4*>(&Vb[(size_t)lr*WW + lc4]);
    float4 vr1 = *reinterpret_cast<const float4*>(&Vb[(size_t)(lr+16)*WW + lc4]);

    float l_i[4] = {0.f, 0.f, 0.f, 0.f};
    ull o2[4][2];
    #pragma unroll
    for (int i = 0; i < 4; i++) { o2[i][0] = 0ull; o2[i][1] = 0ull; }

    const float scale = 1.f/16.f;
    size_t qkbase = (size_t)batch * WW * WW;

    for (int kt = 0; kt < 12; kt++) {
        int k0 = kt * 64;
        __syncthreads();
        // store prefetched tile
        *reinterpret_cast<float4*>(&Ks[lr][lc4])      = kr0;
        *reinterpret_cast<float4*>(&Ks[lr+16][lc4])   = kr1;
        Vs[lc4+0][lr] = vr0.x; Vs[lc4+1][lr] = vr0.y; Vs[lc4+2][lr] = vr0.z; Vs[lc4+3][lr] = vr0.w;
        Vs[lc4+0][lr+16] = vr1.x; Vs[lc4+1][lr+16] = vr1.y; Vs[lc4+2][lr+16] = vr1.z; Vs[lc4+3][lr+16] = vr1.w;
        __syncthreads();

        // ---- S = Q @ K^T ----
        ull acc2[4][2] = {0ull,0ull,0ull,0ull,0ull,0ull,0ull,0ull};
        #pragma unroll
        for (int d = 0; d < 32; d++) {
            ulonglong2 kk2 = *reinterpret_cast<const ulonglong2*>(&Ks[d][tx*4]);
            float4 qv = *reinterpret_cast<const float4*>(&Qs[d][ty*4]);
            ull b0 = bc2(qv.x), b1 = bc2(qv.y), b2 = bc2(qv.z), b3 = bc2(qv.w);
            fma2(acc2[0][0], b0, kk2.x); fma2(acc2[0][1], b0, kk2.y);
            fma2(acc2[1][0], b1, kk2.x); fma2(acc2[1][1], b1, kk2.y);
            fma2(acc2[2][0], b2, kk2.x); fma2(acc2[2][1], b2, kk2.y);
            fma2(acc2[3][0], b3, kk2.x); fma2(acc2[3][1], b3, kk2.y);
        }

        // prefetch next K/V tile (hidden behind epilogue)
        if (kt < 11) {
            int k1 = k0 + 64;
            kr0 = *reinterpret_cast<const float4*>(&Kb[(size_t)lr*WW + k1 + lc4]);
            kr1 = *reinterpret_cast<const float4*>(&Kb[(size_t)(lr+16)*WW + k1 + lc4]);
            vr0 = *reinterpret_cast<const float4*>(&Vb[(size_t)lr*WW + k1 + lc4]);
            vr1 = *reinterpret_cast<const float4*>(&Vb[(size_t)(lr+16)*WW + k1 + lc4]);
        }

        // ---- epilogue: qk write + max-free softmax ----
        #pragma unroll
        for (int i = 0; i < 4; i++) {
            int q = q0 + ty*4 + i;
            size_t row = qkbase + (size_t)q*WW + k0 + tx*4;
            float4 pv = *reinterpret_cast<const float4*>(&prev_qk[row]);
            float2 s01 = up2(acc2[i][0]);
            float2 s23 = up2(acc2[i][1]);
            float s0 = fmaf(s01.x, scale, pv.x);
            float s1 = fmaf(s01.y, scale, pv.y);
            float s2 = fmaf(s23.x, scale, pv.z);
            float s3 = fmaf(s23.y, scale, pv.w);
            *reinterpret_cast<float4*>(&qk_out[row]) = make_float4(s0,s1,s2,s3);

            float p0 = __expf(s0), p1 = __expf(s1);
            float p2 = __expf(s2), p3 = __expf(s3);
            float rs = (p0 + p1) + (p2 + p3);
            #pragma unroll
            for (int o = 8; o > 0; o >>= 1) rs += __shfl_xor_sync(0xffffffffu, rs, o);
            l_i[i] += rs;
            *reinterpret_cast<float4*>(&Ps[ty*4+i][tx*4]) = make_float4(p0,p1,p2,p3);
        }
        __syncthreads();

        // ---- O += P @ V ----
        #pragma unroll
        for (int kb = 0; kb < 8; kb++) {
            int kbase = kx*32 + kb*4;
            float4 pr0 = *reinterpret_cast<const float4*>(&Ps[ty*4+0][kbase]);
            float4 pr1 = *reinterpret_cast<const float4*>(&Ps[ty*4+1][kbase]);
            float4 pr2 = *reinterpret_cast<const float4*>(&Ps[ty*4+2][kbase]);
            float4 pr3 = *reinterpret_cast<const float4*>(&Ps[ty*4+3][kbase]);
            const float* p0f = reinterpret_cast<const float*>(&pr0);
            const float* p1f = reinterpret_cast<const float*>(&pr1);
            const float* p2f = reinterpret_cast<const float*>(&pr2);
            const float* p3f = reinterpret_cast<const float*>(&pr3);
            #pragma unroll
            for (int t = 0; t < 4; t++) {
                ulonglong2 vv = *reinterpret_cast<const ulonglong2*>(&Vs[kbase + t][dq*4]);
                ull w0b = bc2(p0f[t]);
                ull w1b = bc2(p1f[t]);
                ull w2b = bc2(p2f[t]);
                ull w3b = bc2(p3f[t]);
                fma2(o2[0][0], w0b, vv.x); fma2(o2[0][1], w0b, vv.y);
                fma2(o2[1][0], w1b, vv.x); fma2(o2[1][1], w1b, vv.y);
                fma2(o2[2][0], w2b, vv.x); fma2(o2[2][1], w2b, vv.y);
                fma2(o2[3][0], w3b, vv.x); fma2(o2[3][1], w3b, vv.y);
            }
        }
    }

    // ---- finalize ----
    __syncthreads();   // Ps reuse as [d][q] staging
    #pragma unroll
    for (int i = 0; i < 4; i++) {
        float2 a01 = up2(o2[i][0]);
        float2 a23 = up2(o2[i][1]);
        a01.x += __shfl_xor_sync(0xffffffffu, a01.x, 8);
        a01.y += __shfl_xor_sync(0xffffffffu, a01.y, 8);
        a23.x += __shfl_xor_sync(0xffffffffu, a23.x, 8);
        a23.y += __shfl_xor_sync(0xffffffffu, a23.y, 8);
        if (kx == 0) {
            float rl = 1.0f / l_i[i];
            int qc = ty*4 + i;
            Ps[dq*4+0][qc] = a01.x * rl;
            Ps[dq*4+1][qc] = a01.y * rl;
            Ps[dq*4+2][qc] = a23.x * rl;
            Ps[dq*4+3][qc] = a23.y * rl;
        }
    }
    __syncthreads();

    #pragma unroll
    for (int it = 0; it < 2; it++) {
        int li = tid + it*256;
        int d  = li >> 4;
        int c4 = (li & 15) * 4;
        float4 o = *reinterpret_cast<const float4*>(&Ps[d][c4]);
        *reinterpret_cast<float4*>(
            &g_a[((size_t)bmi*FF + h*DHH + d)*WW + q0 + c4]) = o;
    }
}

// =====================================================================
// K5a: o positionwise proj, 128x128 tile, 8x8 f32x2 microtile.
// grid (2, 6, B*CA), block 256
// =====================================================================
__global__ __launch_bounds__(256, 2)
void opw_kernel(const float* __restrict__ x, const float* __restrict__ opw)
{
    int z = blockIdx.z;
    int b = z / CA, c = z % CA;
    const float* A  = opw + (size_t)c*FF*FF;
    const float* Bm = (c < CH) ? (x   + (size_t)(b*CH + c     )*FF*WW)
                               : (g_a + (size_t)(b*AM + c - CH)*FF*WW);
    float* Out = g_o1 + (size_t)(b*CA + c)*FF*WW;

    __shared__ float As[16][132];
    __shared__ float Bs[16][132];

    int g0 = blockIdx.x * 128, w0 = blockIdx.y * 128;
    int tid = threadIdx.x;
    int ty = tid >> 4, tx = tid & 15;

    ull acc2[8][4];
    #pragma unroll
    for (int i = 0; i < 8; i++)
        #pragma unroll
        for (int j = 0; j < 4; j++) acc2[i][j] = 0ull;

    for (int f0 = 0; f0 < FF; f0 += 16) {
        __syncthreads();
        #pragma unroll
        for (int it = 0; it < 2; it++) {
            int li = tid + it*256;
            {
                int r = li >> 2, c4 = (li & 3) * 4;
                float4 v4 = *reinterpret_cast<const float4*>(&A[(size_t)(g0 + r)*FF + f0 + c4]);
                As[c4+0][r] = v4.x; As[c4+1][r] = v4.y; As[c4+2][r] = v4.z; As[c4+3][r] = v4.w;
            }
            {
                int r = li >> 5, c4 = (li & 31) * 4;
                *reinterpret_cast<float4*>(&Bs[r][c4]) =
                    *reinterpret_cast<const float4*>(&Bm[(size_t)(f0 + r)*WW + w0 + c4]);
            }
        }
        __syncthreads();

        #pragma unroll
        for (int kk = 0; kk < 16; kk++) {
            float4 a0 = *reinterpret_cast<const float4*>(&As[kk][ty*8]);
            float4 a1 = *reinterpret_cast<const float4*>(&As[kk][ty*8 + 4]);
            ulonglong2 b0 = *reinterpret_cast<const ulonglong2*>(&Bs[kk][tx*8]);
            ulonglong2 b1 = *reinterpret_cast<const ulonglong2*>(&Bs[kk][tx*8 + 4]);
            ull av0 = bc2(a0.x), av1 = bc2(a0.y), av2 = bc2(a0.z), av3 = bc2(a0.w);
            ull av4 = bc2(a1.x), av5 = bc2(a1.y), av6 = bc2(a1.z), av7 = bc2(a1.w);
            fma2(acc2[0][0], av0, b0.x); fma2(acc2[0][1], av0, b0.y); fma2(acc2[0][2], av0, b1.x); fma2(acc2[0][3], av0, b1.y);
            fma2(acc2[1][0], av1, b0.x); fma2(acc2[1][1], av1, b0.y); fma2(acc2[1][2], av1, b1.x); fma2(acc2[1][3], av1, b1.y);
            fma2(acc2[2][0], av2, b0.x); fma2(acc2[2][1], av2, b0.y); fma2(acc2[2][2], av2, b1.x); fma2(acc2[2][3], av2, b1.y);
            fma2(acc2[3][0], av3, b0.x); fma2(acc2[3][1], av3, b0.y); fma2(acc2[3][2], av3, b1.x); fma2(acc2[3][3], av3, b1.y);
            fma2(acc2[4][0], av4, b0.x); fma2(acc2[4][1], av4, b0.y); fma2(acc2[4][2], av4, b1.x); fma2(acc2[4][3], av4, b1.y);
            fma2(acc2[5][0], av5, b0.x); fma2(acc2[5][1], av5, b0.y); fma2(acc2[5][2], av5, b1.x); fma2(acc2[5][3], av5, b1.y);
            fma2(acc2[6][0], av6, b0.x); fma2(acc2[6][1], av6, b0.y); fma2(acc2[6][2], av6, b1.x); fma2(acc2[6][3], av6, b1.y);
            fma2(acc2[7][0], av7, b0.x); fma2(acc2[7][1], av7, b0.y); fma2(acc2[7][2], av7, b1.x); fma2(acc2[7][3], av7, b1.y);
        }
    }

    #pragma unroll
    for (int i = 0; i < 8; i++) {
        int g = g0 + ty*8 + i;
        float r_[8];
        #pragma unroll
        for (int j = 0; j < 4; j++) {
            float2 f2 = up2(acc2[i][j]);
            r_[2*j] = f2.x; r_[2*j+1] = f2.y;
        }
        float* op = &Out[(size_t)g*WW + w0 + tx*8];
        *reinterpret_cast<float4*>(op)     = make_float4(r_[0], r_[1], r_[2], r_[3]);
        *reinterpret_cast<float4*>(op + 4) = make_float4(r_[4], r_[5], r_[6], r_[7]);
    }
}

// =====================================================================
// K5b: depthwise channel mix (float4)
// =====================================================================
__global__ __launch_bounds__(256)
void mix_kernel(const float* __restrict__ o_dw, float* __restrict__ out)
{
    int idx = blockIdx.x * 256 + threadIdx.x;   // over B*F*W/4
    int b   = idx / (FF*WW/4);
    int gw4 = idx % (FF*WW/4);

    __shared__ float sdw[CH*CA];
    if (threadIdx.x < CH*CA) sdw[threadIdx.x] = o_dw[threadIdx.x];
    __syncthreads();

    float4 vc[CA];
    #pragma unroll
    for (int c = 0; c < CA; c++)
        vc[c] = *reinterpret_cast<const float4*>(&g_o1[(size_t)(b*CA + c)*FF*WW + gw4*4]);

    #pragma unroll
    for (int d = 0; d < CH; d++) {
        float4 s = make_float4(0.f, 0.f, 0.f, 0.f);
        #pragma unroll
        for (int c = 0; c < CA; c++) {
            float wdc = sdw[d*CA + c];
            s.x = fmaf(wdc, vc[c].x, s.x);
            s.y = fmaf(wdc, vc[c].y, s.y);
            s.z = fmaf(wdc, vc[c].z, s.z);
            s.w = fmaf(wdc, vc[c].w, s.w);
        }
        *reinterpret_cast<float4*>(&out[(size_t)(b*CH + d)*FF*WW + gw4*4]) = s;
    }
}

// =====================================================================
extern "C" void kernel_launch(void* const* d_in, const int* in_sizes, int n_in,
                              void* d_out, int out_size)
{
    const float* x       = (const float*)d_in[0];
    const float* prev_qk = (const float*)d_in[1];
    const float* q_pw = (const float*)d_in[4];
    const float* k_pw = (const float*)d_in[7];
    const float* v_pw = (const float*)d_in[10];
    const float* o_pw = (const float*)d_in[11];
    const float* o_dw = (const float*)d_in[12];

    cudaMemcpyToSymbolAsync(c_qcw, d_in[2], AM*CH*9*sizeof(float), 0, cudaMemcpyDeviceToDevice);
    cudaMemcpyToSymbolAsync(c_qcb, d_in[3], AM*sizeof(float),      0, cudaMemcpyDeviceToDevice);
    cudaMemcpyToSymbolAsync(c_kcw, d_in[5], AM*CH*9*sizeof(float), 0, cudaMemcpyDeviceToDevice);
    cudaMemcpyToSymbolAsync(c_kcb, d_in[6], AM*sizeof(float),      0, cudaMemcpyDeviceToDevice);
    cudaMemcpyToSymbolAsync(c_vcw, d_in[8], AM*CH*9*sizeof(float), 0, cudaMemcpyDeviceToDevice);
    cudaMemcpyToSymbolAsync(c_vcb, d_in[9], AM*sizeof(float),      0, cudaMemcpyDeviceToDevice);

    float* out_main = (float*)d_out;                  // (B,CH,F,W)
    float* qk_out   = (float*)d_out + OUT_ELEMS;      // (B,AM,NH,W,W)

    cs_init_kernel<<<dim3((16*WW + 255)/256), 256>>>();
    conv_kernel<<<dim3(FF, BB*AM), 384>>>(x);
    pw_kernel<<<dim3(FF/128, WW/128, 3*BB*AM), 256>>>(q_pw, k_pw, v_pw);
    flash_kernel<<<dim3(WW/64, BB*AM*NHH), 256>>>(prev_qk, qk_out);
    opw_kernel<<<dim3(FF/128, WW/128, BB*CA), 256>>>(x, o_pw);
    mix_kernel<<<dim3(BB*FF*WW/1024), 256>>>(o_dw, out_main);
}

// round 4
// speedup vs baseline: 1.5441x; 1.0899x over previous
#include <cuda_runtime.h>

#define BB  2
#define CH  8
#define AM  8
#define NHH 8
#define FF  256
#define WW  768
#define DHH 32
#define CA  16   // CH + AM

#define YSZ (BB*AM*FF*WW)         // 3,145,728
#define OUT_ELEMS (BB*CH*FF*WW)   // 3,145,728

typedef unsigned long long ull;

// ---- scratch (static device memory; allocation is forbidden) ----
__device__ float g_yq[YSZ];
__device__ float g_yk[YSZ];
__device__ float g_yv[YSZ];
__device__ float g_q [YSZ];   // (b,m, g=h*32+d, w)
__device__ float g_k [YSZ];
__device__ float g_v [YSZ];
__device__ float g_a [YSZ];   // attention result (b,m,f,w)
__device__ float g_o1[BB*CA*FF*WW];
__device__ float2 g_cs[16*WW];  // RoPE table: [e][w] -> (cos, sin)

// conv weights in constant memory
__constant__ float c_qcw[AM*CH*9];
__constant__ float c_kcw[AM*CH*9];
__constant__ float c_vcw[AM*CH*9];
__constant__ float c_qcb[AM];
__constant__ float c_kcb[AM];
__constant__ float c_vcb[AM];

// ---------- packed f32x2 helpers ----------
__device__ __forceinline__ ull bc2(float v) {
    ull r; asm("mov.b64 %0, {%1, %1};" : "=l"(r) : "f"(v)); return r;
}
__device__ __forceinline__ ull pk2(float lo, float hi) {
    ull r; asm("mov.b64 %0, {%1, %2};" : "=l"(r) : "f"(lo), "f"(hi)); return r;
}
__device__ __forceinline__ void fma2(ull& d, ull a, ull b) {
    asm("fma.rn.f32x2 %0, %1, %2, %0;" : "+l"(d) : "l"(a), "l"(b));
}
__device__ __forceinline__ float2 up2(ull v) {
    float lo, hi; asm("mov.b64 {%0, %1}, %2;" : "=f"(lo), "=f"(hi) : "l"(v));
    return make_float2(lo, hi);
}

// =====================================================================
// K0: RoPE cos/sin table init
// =====================================================================
__global__ void cs_init_kernel()
{
    int idx = blockIdx.x * 256 + threadIdx.x;
    if (idx >= 16*WW) return;
    int e = idx / WW, w = idx % WW;
    float inv = expf(-(float)(2*e) * (9.210340371976184f / 32.0f));
    float s, c;
    sincosf((float)w * inv, &s, &c);
    g_cs[idx] = make_float2(c, s);
}

// =====================================================================
// K1: 3x3 conv + bias for q,k,v. 2 outputs/thread via f32x2.
// =====================================================================
__global__ __launch_bounds__(384)
void conv_kernel(const float* __restrict__ x)
{
    int tid = threadIdx.x;
    int w0  = tid * 2;
    int f   = blockIdx.x;
    int bm  = blockIdx.y;
    int m = bm % AM, b = bm / AM;

    ull aq = bc2(c_qcb[m]), ak = bc2(c_kcb[m]), av = bc2(c_vcb[m]);

    #pragma unroll
    for (int ci = 0; ci < CH; ci++) {
        const float* xp = x + (size_t)((b*CH + ci)*FF) * WW;
        #pragma unroll
        for (int kh = 0; kh < 3; kh++) {
            int ff = f + kh - 1;
            if (ff < 0 || ff >= FF) continue;
            const float* xr = xp + ff*WW;
            float xm1 = (w0 > 0)      ? xr[w0-1] : 0.f;
            float2 xc = *reinterpret_cast<const float2*>(&xr[w0]);
            float x2  = (w0+2 < WW)   ? xr[w0+2] : 0.f;
            ull pm = pk2(xm1, xc.x);
            ull p0 = pk2(xc.x, xc.y);
            ull pp = pk2(xc.y, x2);
            int wb = m*72 + ci*9 + kh*3;
            fma2(aq, pm, bc2(c_qcw[wb+0])); fma2(aq, p0, bc2(c_qcw[wb+1])); fma2(aq, pp, bc2(c_qcw[wb+2]));
            fma2(ak, pm, bc2(c_kcw[wb+0])); fma2(ak, p0, bc2(c_kcw[wb+1])); fma2(ak, pp, bc2(c_kcw[wb+2]));
            fma2(av, pm, bc2(c_vcw[wb+0])); fma2(av, p0, bc2(c_vcw[wb+1])); fma2(av, pp, bc2(c_vcw[wb+2]));
        }
    }
    int oid = ((b*AM + m)*FF + f)*WW + w0;
    float2 q2 = up2(aq), k2 = up2(ak), v2 = up2(av);
    *reinterpret_cast<float2*>(&g_yq[oid]) = q2;
    *reinterpret_cast<float2*>(&g_yk[oid]) = k2;
    *reinterpret_cast<float2*>(&g_yv[oid]) = v2;
}

// =====================================================================
// K2: positionwise linear, 128x128 tile, 8x8 microtile, f32x2.
// =====================================================================
__global__ __launch_bounds__(256, 2)
void pw_kernel(const float* __restrict__ qpw,
               const float* __restrict__ kpw,
               const float* __restrict__ vpw)
{
    int z  = blockIdx.z;
    int p  = z / (BB*AM);     // 0=q 1=k 2=v
    int bm = z % (BB*AM);
    int m  = bm % AM;

    const float* A  = (p == 0 ? qpw : (p == 1 ? kpw : vpw)) + (size_t)m*FF*FF;      // (g,f)
    const float* Bm = (p == 0 ? g_yq : (p == 1 ? g_yk : g_yv)) + (size_t)bm*FF*WW;  // (f,w)
    float*      Out = (p == 0 ? g_q : (p == 1 ? g_k : g_v)) + (size_t)bm*FF*WW;     // (g,w)

    __shared__ float  As[16][132];   // [f][g]
    __shared__ float  Bs[16][132];   // [f][w]
    __shared__ float2 Ts[16][128];   // [e][w-local]

    int g0 = blockIdx.x * 128, w0 = blockIdx.y * 128;
    int tid = threadIdx.x;
    int ty = tid >> 4, tx = tid & 15;

    if (p < 2) {
        #pragma unroll
        for (int it = 0; it < 8; it++) {
            int li = tid + it*256;
            int e = li >> 7, tw = li & 127;
            Ts[e][tw] = g_cs[e*WW + w0 + tw];
        }
    }

    ull acc2[8][4];
    #pragma unroll
    for (int i = 0; i < 8; i++)
        #pragma unroll
        for (int j = 0; j < 4; j++) acc2[i][j] = 0ull;

    for (int f0 = 0; f0 < FF; f0 += 16) {
        __syncthreads();
        #pragma unroll
        for (int it = 0; it < 2; it++) {
            int li = tid + it*256;
            {
                int r = li >> 2, c4 = (li & 3) * 4;
                float4 v4 = *reinterpret_cast<const float4*>(&A[(size_t)(g0 + r)*FF + f0 + c4]);
                As[c4+0][r] = v4.x; As[c4+1][r] = v4.y; As[c4+2][r] = v4.z; As[c4+3][r] = v4.w;
            }
            {
                int r = li >> 5, c4 = (li & 31) * 4;
                *reinterpret_cast<float4*>(&Bs[r][c4]) =
                    *reinterpret_cast<const float4*>(&Bm[(size_t)(f0 + r)*WW + w0 + c4]);
            }
        }
        __syncthreads();

        #pragma unroll
        for (int kk = 0; kk < 16; kk++) {
            float4 a0 = *reinterpret_cast<const float4*>(&As[kk][ty*8]);
            float4 a1 = *reinterpret_cast<const float4*>(&As[kk][ty*8 + 4]);
            ulonglong2 b0 = *reinterpret_cast<const ulonglong2*>(&Bs[kk][tx*8]);
            ulonglong2 b1 = *reinterpret_cast<const ulonglong2*>(&Bs[kk][tx*8 + 4]);
            ull av0 = bc2(a0.x), av1 = bc2(a0.y), av2 = bc2(a0.z), av3 = bc2(a0.w);
            ull av4 = bc2(a1.x), av5 = bc2(a1.y), av6 = bc2(a1.z), av7 = bc2(a1.w);
            fma2(acc2[0][0], av0, b0.x); fma2(acc2[0][1], av0, b0.y); fma2(acc2[0][2], av0, b1.x); fma2(acc2[0][3], av0, b1.y);
            fma2(acc2[1][0], av1, b0.x); fma2(acc2[1][1], av1, b0.y); fma2(acc2[1][2], av1, b1.x); fma2(acc2[1][3], av1, b1.y);
            fma2(acc2[2][0], av2, b0.x); fma2(acc2[2][1], av2, b0.y); fma2(acc2[2][2], av2, b1.x); fma2(acc2[2][3], av2, b1.y);
            fma2(acc2[3][0], av3, b0.x); fma2(acc2[3][1], av3, b0.y); fma2(acc2[3][2], av3, b1.x); fma2(acc2[3][3], av3, b1.y);
            fma2(acc2[4][0], av4, b0.x); fma2(acc2[4][1], av4, b0.y); fma2(acc2[4][2], av4, b1.x); fma2(acc2[4][3], av4, b1.y);
            fma2(acc2[5][0], av5, b0.x); fma2(acc2[5][1], av5, b0.y); fma2(acc2[5][2], av5, b1.x); fma2(acc2[5][3], av5, b1.y);
            fma2(acc2[6][0], av6, b0.x); fma2(acc2[6][1], av6, b0.y); fma2(acc2[6][2], av6, b1.x); fma2(acc2[6][3], av6, b1.y);
            fma2(acc2[7][0], av7, b0.x); fma2(acc2[7][1], av7, b0.y); fma2(acc2[7][2], av7, b1.x); fma2(acc2[7][3], av7, b1.y);
        }
    }

    if (p == 2) {
        #pragma unroll
        for (int i = 0; i < 8; i++) {
            int g = g0 + ty*8 + i;
            float r_[8];
            #pragma unroll
            for (int j = 0; j < 4; j++) {
                float2 f2 = up2(acc2[i][j]);
                r_[2*j] = f2.x; r_[2*j+1] = f2.y;
            }
            float* op = &Out[(size_t)g*WW + w0 + tx*8];
            *reinterpret_cast<float4*>(op)     = make_float4(r_[0], r_[1], r_[2], r_[3]);
            *reinterpret_cast<float4*>(op + 4) = make_float4(r_[4], r_[5], r_[6], r_[7]);
        }
    } else {
        #pragma unroll
        for (int ip = 0; ip < 4; ip++) {
            int g = g0 + ty*8 + ip*2;
            int e = (g & 31) >> 1;
            float re[8], ro[8];
            #pragma unroll
            for (int j = 0; j < 4; j++) {
                float2 ve = up2(acc2[ip*2    ][j]);
                float2 vo = up2(acc2[ip*2 + 1][j]);
                int twa = tx*8 + 2*j;
                float2 csa = Ts[e][twa];
                float2 csb = Ts[e][twa + 1];
                re[2*j]   = ve.x*csa.x - vo.x*csa.y;
                ro[2*j]   = vo.x*csa.x + ve.x*csa.y;
                re[2*j+1] = ve.y*csb.x - vo.y*csb.y;
                ro[2*j+1] = vo.y*csb.x + ve.y*csb.y;
            }
            float* oe = &Out[(size_t)g*WW + w0 + tx*8];
            float* oo = &Out[(size_t)(g+1)*WW + w0 + tx*8];
            *reinterpret_cast<float4*>(oe)     = make_float4(re[0], re[1], re[2], re[3]);
            *reinterpret_cast<float4*>(oe + 4) = make_float4(re[4], re[5], re[6], re[7]);
            *reinterpret_cast<float4*>(oo)     = make_float4(ro[0], ro[1], ro[2], ro[3]);
            *reinterpret_cast<float4*>(oo + 4) = make_float4(ro[4], ro[5], ro[6], ro[7]);
        }
    }
}

// =====================================================================
// K3: flash attention v3. q-tile 128, k-tile 64, q-pairs packed f32x2.
// grid (6, 128), block 256, dynamic smem 68608 B.
// Thread grid: ty=tid/16 -> 8 q rows (packed as 4 pairs), tx=tid%16.
//   QK: tx -> 4 k cols.   PV: dsel=tx&7 -> 4 d cols, kx=tx>>3 -> k half.
// =====================================================================
#define FL_SMEM (( 32*132 + 32*68 + 64*36 + 64*132 ) * 4)

__global__ __launch_bounds__(256, 2)
void flash_kernel(const float* __restrict__ prev_qk, float* __restrict__ qk_out)
{
    extern __shared__ float sm[];
    float* Qs = sm;                  // [32][132]  [d][q]
    float* Ks = Qs + 32*132;         // [32][68]   [d][k]
    float* Vs = Ks + 32*68;          // [64][36]   [k][d]
    float* Ps = Vs + 64*36;          // [64][132]  [k][q]  (reused as O staging)

    int q0    = blockIdx.x * 128;
    int batch = blockIdx.y;
    int bmi = batch >> 3, h = batch & 7;
    size_t gbase = ((size_t)bmi*FF + h*32) * WW;
    const float* Qb = g_q + gbase;
    const float* Kb = g_k + gbase;
    const float* Vb = g_v + gbase;

    int tid = threadIdx.x;
    int ty = tid >> 4, tx = tid & 15;
    int dsel = tx & 7, kx = tx >> 3;
    int lr = tid >> 4, lc4 = (tid & 15) * 4;

    // ---- load Q tile: 32 d x 128 q ----
    #pragma unroll
    for (int it = 0; it < 4; it++) {
        int li = tid + it*256;
        int d = li >> 5, c4 = (li & 31) * 4;
        *reinterpret_cast<float4*>(&Qs[d*132 + c4]) =
            *reinterpret_cast<const float4*>(&Qb[(size_t)d*WW + q0 + c4]);
    }

    // ---- prefetch K/V tile 0 ----
    float4 kr0 = *reinterpret_cast<const float4*>(&Kb[(size_t)lr*WW + lc4]);
    float4 kr1 = *reinterpret_cast<const float4*>(&Kb[(size_t)(lr+16)*WW + lc4]);
    float4 vr0 = *reinterpret_cast<const float4*>(&Vb[(size_t)lr*WW + lc4]);
    float4 vr1 = *reinterpret_cast<const float4*>(&Vb[(size_t)(lr+16)*WW + lc4]);

    float l_i[8] = {0,0,0,0,0,0,0,0};
    ull o2[4][4];
    #pragma unroll
    for (int i = 0; i < 4; i++)
        #pragma unroll
        for (int j = 0; j < 4; j++) o2[i][j] = 0ull;

    const float scale = 1.f/16.f;
    size_t qkbase = (size_t)batch * WW * WW;

    for (int kt = 0; kt < 12; kt++) {
        int k0 = kt * 64;
        __syncthreads();
        *reinterpret_cast<float4*>(&Ks[lr*68 + lc4])      = kr0;
        *reinterpret_cast<float4*>(&Ks[(lr+16)*68 + lc4]) = kr1;
        Vs[(lc4+0)*36 + lr] = vr0.x; Vs[(lc4+1)*36 + lr] = vr0.y;
        Vs[(lc4+2)*36 + lr] = vr0.z; Vs[(lc4+3)*36 + lr] = vr0.w;
        Vs[(lc4+0)*36 + lr+16] = vr1.x; Vs[(lc4+1)*36 + lr+16] = vr1.y;
        Vs[(lc4+2)*36 + lr+16] = vr1.z; Vs[(lc4+3)*36 + lr+16] = vr1.w;
        __syncthreads();

        // ---- S = Q @ K^T  (acc[qp][j]: q-pair packed, 4 k cols) ----
        ull acc2[4][4];
        #pragma unroll
        for (int i = 0; i < 4; i++)
            #pragma unroll
            for (int j = 0; j < 4; j++) acc2[i][j] = 0ull;

        #pragma unroll
        for (int d = 0; d < 32; d++) {
            ulonglong2 qA = *reinterpret_cast<const ulonglong2*>(&Qs[d*132 + ty*8]);
            ulonglong2 qB = *reinterpret_cast<const ulonglong2*>(&Qs[d*132 + ty*8 + 4]);
            float4 kv = *reinterpret_cast<const float4*>(&Ks[d*68 + tx*4]);
            ull k0b = bc2(kv.x), k1b = bc2(kv.y), k2b = bc2(kv.z), k3b = bc2(kv.w);
            fma2(acc2[0][0], qA.x, k0b); fma2(acc2[0][1], qA.x, k1b); fma2(acc2[0][2], qA.x, k2b); fma2(acc2[0][3], qA.x, k3b);
            fma2(acc2[1][0], qA.y, k0b); fma2(acc2[1][1], qA.y, k1b); fma2(acc2[1][2], qA.y, k2b); fma2(acc2[1][3], qA.y, k3b);
            fma2(acc2[2][0], qB.x, k0b); fma2(acc2[2][1], qB.x, k1b); fma2(acc2[2][2], qB.x, k2b); fma2(acc2[2][3], qB.x, k3b);
            fma2(acc2[3][0], qB.y, k0b); fma2(acc2[3][1], qB.y, k1b); fma2(acc2[3][2], qB.y, k2b); fma2(acc2[3][3], qB.y, k3b);
        }

        // ---- prefetch next K/V tile ----
        if (kt < 11) {
            int k1 = k0 + 64;
            kr0 = *reinterpret_cast<const float4*>(&Kb[(size_t)lr*WW + k1 + lc4]);
            kr1 = *reinterpret_cast<const float4*>(&Kb[(size_t)(lr+16)*WW + k1 + lc4]);
            vr0 = *reinterpret_cast<const float4*>(&Vb[(size_t)lr*WW + k1 + lc4]);
            vr1 = *reinterpret_cast<const float4*>(&Vb[(size_t)(lr+16)*WW + k1 + lc4]);
        }

        // ---- epilogue: qk output + exp (max-free) ----
        float p[8][4];
        #pragma unroll
        for (int qp = 0; qp < 4; qp++) {
            float2 s0 = up2(acc2[qp][0]);
            float2 s1 = up2(acc2[qp][1]);
            float2 s2 = up2(acc2[qp][2]);
            float2 s3 = up2(acc2[qp][3]);
            int ra = ty*8 + qp*2;
            size_t rowa = qkbase + (size_t)(q0 + ra)*WW + k0 + tx*4;
            float4 pva = *reinterpret_cast<const float4*>(&prev_qk[rowa]);
            float4 pvb = *reinterpret_cast<const float4*>(&prev_qk[rowa + WW]);
            float sa0 = fmaf(s0.x, scale, pva.x), sa1 = fmaf(s1.x, scale, pva.y);
            float sa2 = fmaf(s2.x, scale, pva.z), sa3 = fmaf(s3.x, scale, pva.w);
            float sb0 = fmaf(s0.y, scale, pvb.x), sb1 = fmaf(s1.y, scale, pvb.y);
            float sb2 = fmaf(s2.y, scale, pvb.z), sb3 = fmaf(s3.y, scale, pvb.w);
            *reinterpret_cast<float4*>(&qk_out[rowa])      = make_float4(sa0,sa1,sa2,sa3);
            *reinterpret_cast<float4*>(&qk_out[rowa + WW]) = make_float4(sb0,sb1,sb2,sb3);
            float pa0 = __expf(sa0), pa1 = __expf(sa1), pa2 = __expf(sa2), pa3 = __expf(sa3);
            float pb0 = __expf(sb0), pb1 = __expf(sb1), pb2 = __expf(sb2), pb3 = __expf(sb3);
            p[qp*2  ][0] = pa0; p[qp*2  ][1] = pa1; p[qp*2  ][2] = pa2; p[qp*2  ][3] = pa3;
            p[qp*2+1][0] = pb0; p[qp*2+1][1] = pb1; p[qp*2+1][2] = pb2; p[qp*2+1][3] = pb3;
            l_i[qp*2  ] += (pa0 + pa1) + (pa2 + pa3);
            l_i[qp*2+1] += (pb0 + pb1) + (pb2 + pb3);
        }
        // store P transposed [k][q] (q contiguous)
        #pragma unroll
        for (int j = 0; j < 4; j++) {
            int kr = tx*4 + j;
            *reinterpret_cast<float4*>(&Ps[kr*132 + ty*8]) =
                make_float4(p[0][j], p[1][j], p[2][j], p[3][j]);
            *reinterpret_cast<float4*>(&Ps[kr*132 + ty*8 + 4]) =
                make_float4(p[4][j], p[5][j], p[6][j], p[7][j]);
        }
        __syncthreads();

        // ---- O += P @ V  (thread: 8q (4 pairs) x 4 d, k over kx half) ----
        #pragma unroll
        for (int kk = 0; kk < 32; kk++) {
            int k = kx*32 + kk;
            ulonglong2 pA = *reinterpret_cast<const ulonglong2*>(&Ps[k*132 + ty*8]);
            ulonglong2 pB = *reinterpret_cast<const ulonglong2*>(&Ps[k*132 + ty*8 + 4]);
            float4 vv = *reinterpret_cast<const float4*>(&Vs[k*36 + dsel*4]);
            ull v0 = bc2(vv.x), v1 = bc2(vv.y), v2 = bc2(vv.z), v3 = bc2(vv.w);
            fma2(o2[0][0], pA.x, v0); fma2(o2[0][1], pA.x, v1); fma2(o2[0][2], pA.x, v2); fma2(o2[0][3], pA.x, v3);
            fma2(o2[1][0], pA.y, v0); fma2(o2[1][1], pA.y, v1); fma2(o2[1][2], pA.y, v2); fma2(o2[1][3], pA.y, v3);
            fma2(o2[2][0], pB.x, v0); fma2(o2[2][1], pB.x, v1); fma2(o2[2][2], pB.x, v2); fma2(o2[2][3], pB.x, v3);
            fma2(o2[3][0], pB.y, v0); fma2(o2[3][1], pB.y, v1); fma2(o2[3][2], pB.y, v2); fma2(o2[3][3], pB.y, v3);
        }
    }

    // ---- reduce k-halves (lanes differing in tx bit3 = lane bit3) ----
    #pragma unroll
    for (int i = 0; i < 4; i++)
        #pragma unroll
        for (int j = 0; j < 4; j++) {
            float2 v = up2(o2[i][j]);
            v.x += __shfl_xor_sync(0xffffffffu, v.x, 8);
            v.y += __shfl_xor_sync(0xffffffffu, v.y, 8);
            o2[i][j] = pk2(v.x, v.y);
        }
    // ---- reduce l over 16 tx lanes ----
    #pragma unroll
    for (int r = 0; r < 8; r++) {
        float lv = l_i[r];
        lv += __shfl_xor_sync(0xffffffffu, lv, 1);
        lv += __shfl_xor_sync(0xffffffffu, lv, 2);
        lv += __shfl_xor_sync(0xffffffffu, lv, 4);
        lv += __shfl_xor_sync(0xffffffffu, lv, 8);
        l_i[r] = lv;
    }

    __syncthreads();   // all PV reads of Ps done; reuse as [d][q] staging
    if (kx == 0) {
        float rl[8];
        #pragma unroll
        for (int r = 0; r < 8; r++) rl[r] = 1.0f / l_i[r];
        #pragma unroll
        for (int qp = 0; qp < 4; qp++)
            #pragma unroll
            for (int j = 0; j < 4; j++) {
                float2 v = up2(o2[qp][j]);
                int d = dsel*4 + j;
                int qq = ty*8 + qp*2;
                Ps[d*132 + qq]     = v.x * rl[qp*2];
                Ps[d*132 + qq + 1] = v.y * rl[qp*2+1];
            }
    }
    __syncthreads();

    #pragma unroll
    for (int it = 0; it < 4; it++) {
        int li = tid + it*256;
        int d = li >> 5, c4 = (li & 31) * 4;
        *reinterpret_cast<float4*>(&g_a[((size_t)bmi*FF + h*DHH + d)*WW + q0 + c4]) =
            *reinterpret_cast<const float4*>(&Ps[d*132 + c4]);
    }
}

// =====================================================================
// K5a: o positionwise proj, 128x128 tile, 8x8 f32x2 microtile.
// =====================================================================
__global__ __launch_bounds__(256, 2)
void opw_kernel(const float* __restrict__ x, const float* __restrict__ opw)
{
    int z = blockIdx.z;
    int b = z / CA, c = z % CA;
    const float* A  = opw + (size_t)c*FF*FF;
    const float* Bm = (c < CH) ? (x   + (size_t)(b*CH + c     )*FF*WW)
                               : (g_a + (size_t)(b*AM + c - CH)*FF*WW);
    float* Out = g_o1 + (size_t)(b*CA + c)*FF*WW;

    __shared__ float As[16][132];
    __shared__ float Bs[16][132];

    int g0 = blockIdx.x * 128, w0 = blockIdx.y * 128;
    int tid = threadIdx.x;
    int ty = tid >> 4, tx = tid & 15;

    ull acc2[8][4];
    #pragma unroll
    for (int i = 0; i < 8; i++)
        #pragma unroll
        for (int j = 0; j < 4; j++) acc2[i][j] = 0ull;

    for (int f0 = 0; f0 < FF; f0 += 16) {
        __syncthreads();
        #pragma unroll
        for (int it = 0; it < 2; it++) {
            int li = tid + it*256;
            {
                int r = li >> 2, c4 = (li & 3) * 4;
                float4 v4 = *reinterpret_cast<const float4*>(&A[(size_t)(g0 + r)*FF + f0 + c4]);
                As[c4+0][r] = v4.x; As[c4+1][r] = v4.y; As[c4+2][r] = v4.z; As[c4+3][r] = v4.w;
            }
            {
                int r = li >> 5, c4 = (li & 31) * 4;
                *reinterpret_cast<float4*>(&Bs[r][c4]) =
                    *reinterpret_cast<const float4*>(&Bm[(size_t)(f0 + r)*WW + w0 + c4]);
            }
        }
        __syncthreads();

        #pragma unroll
        for (int kk = 0; kk < 16; kk++) {
            float4 a0 = *reinterpret_cast<const float4*>(&As[kk][ty*8]);
            float4 a1 = *reinterpret_cast<const float4*>(&As[kk][ty*8 + 4]);
            ulonglong2 b0 = *reinterpret_cast<const ulonglong2*>(&Bs[kk][tx*8]);
            ulonglong2 b1 = *reinterpret_cast<const ulonglong2*>(&Bs[kk][tx*8 + 4]);
            ull av0 = bc2(a0.x), av1 = bc2(a0.y), av2 = bc2(a0.z), av3 = bc2(a0.w);
            ull av4 = bc2(a1.x), av5 = bc2(a1.y), av6 = bc2(a1.z), av7 = bc2(a1.w);
            fma2(acc2[0][0], av0, b0.x); fma2(acc2[0][1], av0, b0.y); fma2(acc2[0][2], av0, b1.x); fma2(acc2[0][3], av0, b1.y);
            fma2(acc2[1][0], av1, b0.x); fma2(acc2[1][1], av1, b0.y); fma2(acc2[1][2], av1, b1.x); fma2(acc2[1][3], av1, b1.y);
            fma2(acc2[2][0], av2, b0.x); fma2(acc2[2][1], av2, b0.y); fma2(acc2[2][2], av2, b1.x); fma2(acc2[2][3], av2, b1.y);
            fma2(acc2[3][0], av3, b0.x); fma2(acc2[3][1], av3, b0.y); fma2(acc2[3][2], av3, b1.x); fma2(acc2[3][3], av3, b1.y);
            fma2(acc2[4][0], av4, b0.x); fma2(acc2[4][1], av4, b0.y); fma2(acc2[4][2], av4, b1.x); fma2(acc2[4][3], av4, b1.y);
            fma2(acc2[5][0], av5, b0.x); fma2(acc2[5][1], av5, b0.y); fma2(acc2[5][2], av5, b1.x); fma2(acc2[5][3], av5, b1.y);
            fma2(acc2[6][0], av6, b0.x); fma2(acc2[6][1], av6, b0.y); fma2(acc2[6][2], av6, b1.x); fma2(acc2[6][3], av6, b1.y);
            fma2(acc2[7][0], av7, b0.x); fma2(acc2[7][1], av7, b0.y); fma2(acc2[7][2], av7, b1.x); fma2(acc2[7][3], av7, b1.y);
        }
    }

    #pragma unroll
    for (int i = 0; i < 8; i++) {
        int g = g0 + ty*8 + i;
        float r_[8];
        #pragma unroll
        for (int j = 0; j < 4; j++) {
            float2 f2 = up2(acc2[i][j]);
            r_[2*j] = f2.x; r_[2*j+1] = f2.y;
        }
        float* op = &Out[(size_t)g*WW + w0 + tx*8];
        *reinterpret_cast<float4*>(op)     = make_float4(r_[0], r_[1], r_[2], r_[3]);
        *reinterpret_cast<float4*>(op + 4) = make_float4(r_[4], r_[5], r_[6], r_[7]);
    }
}

// =====================================================================
// K5b: depthwise channel mix (float4)
// =====================================================================
__global__ __launch_bounds__(256)
void mix_kernel(const float* __restrict__ o_dw, float* __restrict__ out)
{
    int idx = blockIdx.x * 256 + threadIdx.x;
    int b   = idx / (FF*WW/4);
    int gw4 = idx % (FF*WW/4);

    __shared__ float sdw[CH*CA];
    if (threadIdx.x < CH*CA) sdw[threadIdx.x] = o_dw[threadIdx.x];
    __syncthreads();

    float4 vc[CA];
    #pragma unroll
    for (int c = 0; c < CA; c++)
        vc[c] = *reinterpret_cast<const float4*>(&g_o1[(size_t)(b*CA + c)*FF*WW + gw4*4]);

    #pragma unroll
    for (int d = 0; d < CH; d++) {
        float4 s = make_float4(0.f, 0.f, 0.f, 0.f);
        #pragma unroll
        for (int c = 0; c < CA; c++) {
            float wdc = sdw[d*CA + c];
            s.x = fmaf(wdc, vc[c].x, s.x);
            s.y = fmaf(wdc, vc[c].y, s.y);
            s.z = fmaf(wdc, vc[c].z, s.z);
            s.w = fmaf(wdc, vc[c].w, s.w);
        }
        *reinterpret_cast<float4*>(&out[(size_t)(b*CH + d)*FF*WW + gw4*4]) = s;
    }
}

// =====================================================================
extern "C" void kernel_launch(void* const* d_in, const int* in_sizes, int n_in,
                              void* d_out, int out_size)
{
    const float* x       = (const float*)d_in[0];
    const float* prev_qk = (const float*)d_in[1];
    const float* q_pw = (const float*)d_in[4];
    const float* k_pw = (const float*)d_in[7];
    const float* v_pw = (const float*)d_in[10];
    const float* o_pw = (const float*)d_in[11];
    const float* o_dw = (const float*)d_in[12];

    cudaMemcpyToSymbolAsync(c_qcw, d_in[2], AM*CH*9*sizeof(float), 0, cudaMemcpyDeviceToDevice);
    cudaMemcpyToSymbolAsync(c_qcb, d_in[3], AM*sizeof(float),      0, cudaMemcpyDeviceToDevice);
    cudaMemcpyToSymbolAsync(c_kcw, d_in[5], AM*CH*9*sizeof(float), 0, cudaMemcpyDeviceToDevice);
    cudaMemcpyToSymbolAsync(c_kcb, d_in[6], AM*sizeof(float),      0, cudaMemcpyDeviceToDevice);
    cudaMemcpyToSymbolAsync(c_vcw, d_in[8], AM*CH*9*sizeof(float), 0, cudaMemcpyDeviceToDevice);
    cudaMemcpyToSymbolAsync(c_vcb, d_in[9], AM*sizeof(float),      0, cudaMemcpyDeviceToDevice);

    static bool attr_set = false;
    if (!attr_set) {
        cudaFuncSetAttribute(flash_kernel, cudaFuncAttributeMaxDynamicSharedMemorySize, FL_SMEM);
        attr_set = true;
    }

    float* out_main = (float*)d_out;                  // (B,CH,F,W)
    float* qk_out   = (float*)d_out + OUT_ELEMS;      // (B,AM,NH,W,W)

    cs_init_kernel<<<dim3((16*WW + 255)/256), 256>>>();
    conv_kernel<<<dim3(FF, BB*AM), 384>>>(x);
    pw_kernel<<<dim3(FF/128, WW/128, 3*BB*AM), 256>>>(q_pw, k_pw, v_pw);
    flash_kernel<<<dim3(WW/128, BB*AM*NHH), 256, FL_SMEM>>>(prev_qk, qk_out);
    opw_kernel<<<dim3(FF/128, WW/128, BB*CA), 256>>>(x, o_pw);
    mix_kernel<<<dim3(BB*FF*WW/1024), 256>>>(o_dw, out_main);
}